// round 1
// baseline (speedup 1.0000x reference)
#include <cuda_runtime.h>
#include <math.h>

// Problem dims (fixed per reference)
#define NROWS 8192
#define NFEAT 512
#define NHID  256
#define NCAT  768   // NHID + NFEAT

// ---------------------------------------------------------------------------
// Scratch (static device globals: the sanctioned no-alloc workaround)
// ---------------------------------------------------------------------------
__device__ float g_xw [NROWS * NHID];   // x @ gc1_w
__device__ float g_h1 [NROWS * NHID];   // relu(adj0 @ xw + b1)
__device__ float g_h1w[NROWS * NHID];   // h1 @ gc2_w
__device__ float g_cat[NROWS * NCAT];   // [h2 | target_feats]
__device__ float g_o4 [NROWS * NCAT];
__device__ float g_o5 [NROWS * NCAT];

// ---------------------------------------------------------------------------
// Tiled fp32 GEMM: C[M,N] = A[M,K] @ B[K,N] (+bias) (+relu), row-major.
// BM=BN=128, BK=16, 256 threads, 8x8 register tile per thread.
// Requires: M%128==0, N%128==0, K%16==0 (true for all calls here).
// ---------------------------------------------------------------------------
template <bool RELU, bool BIAS>
__global__ __launch_bounds__(256, 1)
void sgemm128(int M, int N, int K, int ldc,
              const float* __restrict__ A,
              const float* __restrict__ B,
              const float* __restrict__ bias,
              float* __restrict__ C)
{
    constexpr int BM = 128, BN = 128, BK = 16;
    __shared__ float As[BK][BM];   // stored transposed for broadcast reads
    __shared__ float Bs[BK][BN];

    const int bx  = blockIdx.x;            // N-tile
    const int by  = blockIdx.y;            // M-tile
    const int tid = threadIdx.x;
    const int tx  = tid & 15;              // 16 col groups
    const int ty  = tid >> 4;              // 16 row groups

    const float* Ab = A + (size_t)by * BM * K;
    const float* Bb = B + (size_t)bx * BN;

    float acc[8][8];
    #pragma unroll
    for (int i = 0; i < 8; i++)
        #pragma unroll
        for (int j = 0; j < 8; j++) acc[i][j] = 0.0f;

    for (int k0 = 0; k0 < K; k0 += BK) {
        // Cooperative loads: 512 float4 per operand tile, 2 per thread.
        #pragma unroll
        for (int i = 0; i < 2; i++) {
            const int f = tid + i * 256;
            // A tile: 128 rows x 16 cols  (4 float4 per row)
            const int ar  = f >> 2;
            const int ac4 = (f & 3) << 2;
            float4 av = *(const float4*)(Ab + (size_t)ar * K + k0 + ac4);
            As[ac4 + 0][ar] = av.x;
            As[ac4 + 1][ar] = av.y;
            As[ac4 + 2][ar] = av.z;
            As[ac4 + 3][ar] = av.w;
            // B tile: 16 rows x 128 cols (32 float4 per row)
            const int br  = f >> 5;
            const int bc4 = (f & 31) << 2;
            *(float4*)&Bs[br][bc4] =
                *(const float4*)(Bb + (size_t)(k0 + br) * N + bc4);
        }
        __syncthreads();

        #pragma unroll
        for (int k = 0; k < BK; k++) {
            float a[8], b[8];
            #pragma unroll
            for (int i = 0; i < 8; i++) a[i] = As[k][ty * 8 + i];
            #pragma unroll
            for (int j = 0; j < 8; j++) b[j] = Bs[k][tx * 8 + j];
            #pragma unroll
            for (int i = 0; i < 8; i++)
                #pragma unroll
                for (int j = 0; j < 8; j++)
                    acc[i][j] = fmaf(a[i], b[j], acc[i][j]);
        }
        __syncthreads();
    }

    // Epilogue
    const int row0 = by * BM + ty * 8;
    const int col0 = bx * BN + tx * 8;
    float bv[8];
    #pragma unroll
    for (int j = 0; j < 8; j++) bv[j] = BIAS ? bias[col0 + j] : 0.0f;

    #pragma unroll
    for (int i = 0; i < 8; i++) {
        float* Crow = C + (size_t)(row0 + i) * ldc + col0;
        #pragma unroll
        for (int j = 0; j < 8; j += 4) {
            float4 v;
            v.x = acc[i][j + 0] + bv[j + 0];
            v.y = acc[i][j + 1] + bv[j + 1];
            v.z = acc[i][j + 2] + bv[j + 2];
            v.w = acc[i][j + 3] + bv[j + 3];
            if (RELU) {
                v.x = fmaxf(v.x, 0.0f); v.y = fmaxf(v.y, 0.0f);
                v.z = fmaxf(v.z, 0.0f); v.w = fmaxf(v.w, 0.0f);
            }
            *(float4*)(Crow + j) = v;
        }
    }
}

// ---------------------------------------------------------------------------
// Copy target_feats [NROWS, NFEAT] into cat columns [NHID, NCAT)
// ---------------------------------------------------------------------------
__global__ void concat_copy(const float* __restrict__ target, float* __restrict__ cat)
{
    int idx = blockIdx.x * blockDim.x + threadIdx.x;          // in float4 units
    int total4 = NROWS * NFEAT / 4;
    if (idx >= total4) return;
    int r = idx / (NFEAT / 4);
    int c4 = idx % (NFEAT / 4);
    const float4 v = ((const float4*)target)[idx];
    *(float4*)(cat + (size_t)r * NCAT + NHID + c4 * 4) = v;
}

// ---------------------------------------------------------------------------
// Row-wise log_softmax over NFEAT=512 columns, in-place capable.
// One block (256 threads) per row.
// ---------------------------------------------------------------------------
__global__ __launch_bounds__(256) void log_softmax_rows(float* __restrict__ io)
{
    const int row = blockIdx.x;
    float* x = io + (size_t)row * NFEAT;
    const int tid = threadIdx.x;
    __shared__ float red[8];

    // row max
    float m = -INFINITY;
    for (int c = tid; c < NFEAT; c += 256) m = fmaxf(m, x[c]);
    #pragma unroll
    for (int o = 16; o; o >>= 1) m = fmaxf(m, __shfl_xor_sync(0xFFFFFFFFu, m, o));
    if ((tid & 31) == 0) red[tid >> 5] = m;
    __syncthreads();
    float rowmax = red[0];
    #pragma unroll
    for (int i = 1; i < 8; i++) rowmax = fmaxf(rowmax, red[i]);
    __syncthreads();

    // sum exp
    float s = 0.0f;
    for (int c = tid; c < NFEAT; c += 256) s += expf(x[c] - rowmax);
    #pragma unroll
    for (int o = 16; o; o >>= 1) s += __shfl_xor_sync(0xFFFFFFFFu, s, o);
    if ((tid & 31) == 0) red[tid >> 5] = s;
    __syncthreads();
    float tot = 0.0f;
    #pragma unroll
    for (int i = 0; i < 8; i++) tot += red[i];
    const float lse = logf(tot) + rowmax;

    for (int c = tid; c < NFEAT; c += 256) x[c] = x[c] - lse;
}

// ---------------------------------------------------------------------------
// Launch
// ---------------------------------------------------------------------------
extern "C" void kernel_launch(void* const* d_in, const int* in_sizes, int n_in,
                              void* d_out, int out_size)
{
    const float* x       = (const float*)d_in[0];
    const float* target  = (const float*)d_in[1];
    const float* adj0    = (const float*)d_in[2];
    const float* adj1    = (const float*)d_in[3];
    const float* gc1_w   = (const float*)d_in[4];
    const float* gc1_b   = (const float*)d_in[5];
    const float* gc2_w   = (const float*)d_in[6];
    const float* gc2_b   = (const float*)d_in[7];
    const float* lin1_w  = (const float*)d_in[8];
    const float* lin1_b  = (const float*)d_in[9];
    const float* lin2_w  = (const float*)d_in[10];
    const float* lin2_b  = (const float*)d_in[11];
    const float* lin3_w  = (const float*)d_in[12];
    const float* lin3_b  = (const float*)d_in[13];
    float* out = (float*)d_out;

    float *xw, *h1, *h1w, *cat, *o4, *o5;
    cudaGetSymbolAddress((void**)&xw,  g_xw);
    cudaGetSymbolAddress((void**)&h1,  g_h1);
    cudaGetSymbolAddress((void**)&h1w, g_h1w);
    cudaGetSymbolAddress((void**)&cat, g_cat);
    cudaGetSymbolAddress((void**)&o4,  g_o4);
    cudaGetSymbolAddress((void**)&o5,  g_o5);

    const dim3 blk(256);

    // 1. xw = x @ gc1_w                               [8192,512]@[512,256]
    sgemm128<false, false><<<dim3(NHID / 128, NROWS / 128), blk>>>(
        NROWS, NHID, NFEAT, NHID, x, gc1_w, nullptr, xw);

    // 2. h1 = relu(adj0 @ xw + gc1_b)                 [8192,8192]@[8192,256]
    sgemm128<true, true><<<dim3(NHID / 128, NROWS / 128), blk>>>(
        NROWS, NHID, NROWS, NHID, adj0, xw, gc1_b, h1);

    // 3. h1w = h1 @ gc2_w                             [8192,256]@[256,256]
    sgemm128<false, false><<<dim3(NHID / 128, NROWS / 128), blk>>>(
        NROWS, NHID, NHID, NHID, h1, gc2_w, nullptr, h1w);

    // 4. cat[:, :256] = adj1 @ h1w + gc2_b  (ldc=768) [8192,8192]@[8192,256]
    sgemm128<false, true><<<dim3(NHID / 128, NROWS / 128), blk>>>(
        NROWS, NHID, NROWS, NCAT, adj1, h1w, gc2_b, cat);

    // 5. cat[:, 256:768] = target_feats
    concat_copy<<<(NROWS * NFEAT / 4 + 255) / 256, blk>>>(target, cat);

    // 6. o4 = relu(cat @ lin1_w + lin1_b)             [8192,768]@[768,768]
    sgemm128<true, true><<<dim3(NCAT / 128, NROWS / 128), blk>>>(
        NROWS, NCAT, NCAT, NCAT, cat, lin1_w, lin1_b, o4);

    // 7. o5 = relu(o4 @ lin2_w + lin2_b)
    sgemm128<true, true><<<dim3(NCAT / 128, NROWS / 128), blk>>>(
        NROWS, NCAT, NCAT, NCAT, o4, lin2_w, lin2_b, o5);

    // 8. out = o5 @ lin3_w + lin3_b                   [8192,768]@[768,512]
    sgemm128<false, true><<<dim3(NFEAT / 128, NROWS / 128), blk>>>(
        NROWS, NFEAT, NCAT, NFEAT, o5, lin3_w, lin3_b, out);

    // 9. log_softmax in-place on out
    log_softmax_rows<<<NROWS, blk>>>(out);
}

// round 3
// speedup vs baseline: 3.7852x; 3.7852x over previous
#include <cuda_runtime.h>
#include <math.h>
#include <stdint.h>

// Problem dims (fixed per reference)
#define NROWS 8192
#define NFEAT 512
#define NHID  256
#define NCAT  768   // NHID + NFEAT

// ---------------------------------------------------------------------------
// Scratch (static device globals: sanctioned no-alloc workaround)
// ---------------------------------------------------------------------------
__device__ float g_xw  [NROWS * NHID];
__device__ float g_xwT [NHID * NROWS];
__device__ float g_h1  [NROWS * NHID];
__device__ float g_h1w [NROWS * NHID];
__device__ float g_h1wT[NHID * NROWS];
__device__ float g_cat [NROWS * NCAT];
__device__ float g_o4  [NROWS * NCAT];
__device__ float g_o5  [NROWS * NCAT];
__device__ float g_w1T [NHID * NFEAT];
__device__ float g_w2T [NHID * NHID];
__device__ float g_l1T [NCAT * NCAT];
__device__ float g_l2T [NCAT * NCAT];
__device__ float g_l3T [NFEAT * NCAT];

// ---------------------------------------------------------------------------
// Helpers (baseline PTX only: cp.async / ldmatrix / mma.sync — no tcgen05)
// ---------------------------------------------------------------------------
__device__ __forceinline__ uint32_t smem_u32(const void* p) {
    uint32_t a;
    asm("{ .reg .u64 t; cvta.to.shared.u64 t, %1; cvt.u32.u64 %0, t; }"
        : "=r"(a) : "l"(p));
    return a;
}

__device__ __forceinline__ void cpasync16(uint32_t dst, const void* src) {
    asm volatile("cp.async.cg.shared.global [%0], [%1], 16;"
                 :: "r"(dst), "l"(src));
}
__device__ __forceinline__ void cp_commit() {
    asm volatile("cp.async.commit_group;" ::: "memory");
}
__device__ __forceinline__ void cp_wait3() {
    asm volatile("cp.async.wait_group 3;" ::: "memory");
}
__device__ __forceinline__ void cp_wait0() {
    asm volatile("cp.async.wait_group 0;" ::: "memory");
}

__device__ __forceinline__ void ldsm_x4(uint32_t* r, uint32_t addr) {
    asm volatile("ldmatrix.sync.aligned.m8n8.x4.shared.b16 {%0,%1,%2,%3}, [%4];"
                 : "=r"(r[0]), "=r"(r[1]), "=r"(r[2]), "=r"(r[3]) : "r"(addr));
}
__device__ __forceinline__ void ldsm_x2(uint32_t* r, uint32_t addr) {
    asm volatile("ldmatrix.sync.aligned.m8n8.x2.shared.b16 {%0,%1}, [%2];"
                 : "=r"(r[0]), "=r"(r[1]) : "r"(addr));
}

__device__ __forceinline__ void mma_tf32(float* c, const uint32_t* a, const uint32_t* b) {
    asm volatile(
        "mma.sync.aligned.m16n8k8.row.col.f32.tf32.tf32.f32 "
        "{%0,%1,%2,%3}, {%4,%5,%6,%7}, {%8,%9}, {%0,%1,%2,%3};"
        : "+f"(c[0]), "+f"(c[1]), "+f"(c[2]), "+f"(c[3])
        : "r"(a[0]), "r"(a[1]), "r"(a[2]), "r"(a[3]), "r"(b[0]), "r"(b[1]));
}

// ---------------------------------------------------------------------------
// TF32 mma.sync GEMM: C[M,N] = A[M,K] @ Bt[N,K]^T (+bias)(+relu)
// A row-major [M,K], Bt row-major [N,K] (== B col-major), C with given ldc.
// BM=BN=128, BK=32, 256 threads (8 warps, 2x4), warp tile 64x32.
// Requires M%128==0, N%128==0, K%32==0.
// ---------------------------------------------------------------------------
#define BM 128
#define BN 128
#define BK 32
#define STAGES 4
#define ROW_BYTES 144                      // 32 floats + 4 pad (16B aligned)
#define A_REGION (BM * ROW_BYTES)          // 18432
#define STAGE_BYTES (2 * A_REGION)         // 36864
#define DYN_SMEM (STAGES * STAGE_BYTES)    // 147456

__device__ __forceinline__ void load_tile(uint32_t smem, int tile, int tid,
                                          const float* Arow, const float* Brow,
                                          int K) {
    const int k0 = tile * BK;
    const uint32_t abase = smem + (uint32_t)(tile % STAGES) * STAGE_BYTES;
    const uint32_t bbase = abase + A_REGION;
    // A: 128 rows x 8 chunks(16B) = 1024 chunks; 4 per thread
    #pragma unroll
    for (int i = 0; i < 4; i++) {
        const int c = tid + i * 256;
        const int row = c >> 3, col16 = c & 7;
        cpasync16(abase + row * ROW_BYTES + col16 * 16,
                  Arow + (size_t)row * K + k0 + col16 * 4);
    }
    // B: identical shape
    #pragma unroll
    for (int i = 0; i < 4; i++) {
        const int c = tid + i * 256;
        const int row = c >> 3, col16 = c & 7;
        cpasync16(bbase + row * ROW_BYTES + col16 * 16,
                  Brow + (size_t)row * K + k0 + col16 * 4);
    }
}

template <bool RELU, bool BIAS>
__global__ __launch_bounds__(256, 1)
void tf32_gemm(int K, int ldc,
               const float* __restrict__ A,
               const float* __restrict__ Bt,
               const float* __restrict__ bias,
               float* __restrict__ C)
{
    extern __shared__ __align__(16) uint8_t dsraw[];
    const uint32_t smem = smem_u32(dsraw);

    const int tid  = threadIdx.x;
    const int wid  = tid >> 5;
    const int lane = tid & 31;
    const int wm   = wid >> 2;        // 0..1  (64-row band)
    const int wn   = wid & 3;         // 0..3  (32-col band)
    const int m0   = blockIdx.y * BM;
    const int n0   = blockIdx.x * BN;
    const int KT   = K / BK;

    const float* Arow = A  + (size_t)m0 * K;
    const float* Brow = Bt + (size_t)n0 * K;

    float acc[4][4][4];
    #pragma unroll
    for (int mt = 0; mt < 4; mt++)
        #pragma unroll
        for (int nt = 0; nt < 4; nt++)
            #pragma unroll
            for (int i = 0; i < 4; i++) acc[mt][nt][i] = 0.0f;

    // Per-lane ldmatrix base offsets (within a stage)
    // A frag (x4): lanes 0-7 rows+0 k+0 | 8-15 rows+8 k+0 | 16-23 rows+0 k+4 | 24-31 rows+8 k+4
    const uint32_t aOff = (uint32_t)(wm * 64 + (lane & 15)) * ROW_BYTES
                        + (uint32_t)(lane >> 4) * 16;
    // B frag (x2): lanes 0-7 rows n+0..7 k+0 | lanes 8-15 same rows k+4 (others ignored)
    const uint32_t bOff = (uint32_t)(wn * 32 + (lane & 7)) * ROW_BYTES
                        + (uint32_t)((lane >> 3) & 1) * 16;

    // Prologue: prefetch tiles 0..2
    for (int tt = 0; tt < 3; tt++) {
        load_tile(smem, tt, tid, Arow, Brow, K);
        cp_commit();
    }

    for (int t = 0; t < KT; t++) {
        __syncthreads();                       // stage (t+3)%4 free for overwrite
        if (t + 3 < KT) load_tile(smem, t + 3, tid, Arow, Brow, K);
        cp_commit();
        cp_wait3();                            // tile t landed (this thread)
        __syncthreads();                       // all threads' chunks visible

        const uint32_t sA = smem + (uint32_t)(t % STAGES) * STAGE_BYTES;
        const uint32_t sB = sA + A_REGION;
        const uint32_t aBase = sA + aOff;
        const uint32_t bBase = sB + bOff;

        #pragma unroll
        for (int ks = 0; ks < 4; ks++) {
            uint32_t af[4][4], bf[4][2];
            #pragma unroll
            for (int mt = 0; mt < 4; mt++)
                ldsm_x4(af[mt], aBase + mt * (16 * ROW_BYTES) + ks * 32);
            #pragma unroll
            for (int nt = 0; nt < 4; nt++)
                ldsm_x2(bf[nt], bBase + nt * (8 * ROW_BYTES) + ks * 32);
            #pragma unroll
            for (int mt = 0; mt < 4; mt++)
                #pragma unroll
                for (int nt = 0; nt < 4; nt++)
                    mma_tf32(acc[mt][nt], af[mt], bf[nt]);
        }
    }
    cp_wait0();

    // Epilogue: direct STG.64 per (row, col-pair)
    const int rbase = m0 + wm * 64 + (lane >> 2);
    const int cbase = n0 + wn * 32 + 2 * (lane & 3);
    #pragma unroll
    for (int mt = 0; mt < 4; mt++) {
        #pragma unroll
        for (int nt = 0; nt < 4; nt++) {
            const int col = cbase + nt * 8;
            float b0 = 0.0f, b1 = 0.0f;
            if (BIAS) { b0 = bias[col]; b1 = bias[col + 1]; }
            float v0 = acc[mt][nt][0] + b0;
            float v1 = acc[mt][nt][1] + b1;
            float v2 = acc[mt][nt][2] + b0;
            float v3 = acc[mt][nt][3] + b1;
            if (RELU) {
                v0 = fmaxf(v0, 0.0f); v1 = fmaxf(v1, 0.0f);
                v2 = fmaxf(v2, 0.0f); v3 = fmaxf(v3, 0.0f);
            }
            const int row = rbase + mt * 16;
            *(float2*)(C + (size_t)row * ldc + col)       = make_float2(v0, v1);
            *(float2*)(C + (size_t)(row + 8) * ldc + col) = make_float2(v2, v3);
        }
    }
}

// ---------------------------------------------------------------------------
// 32x32 tiled transpose: out[C,R] = in[R,C]^T   (R,C multiples of 32)
// ---------------------------------------------------------------------------
__global__ __launch_bounds__(256) void transpose_k(const float* __restrict__ in,
                                                   float* __restrict__ out,
                                                   int R, int C)
{
    __shared__ float t[32][33];
    const int bx = blockIdx.x * 32;   // C dim
    const int by = blockIdx.y * 32;   // R dim
    const int txx = threadIdx.x, tyy = threadIdx.y;   // (32, 8)
    #pragma unroll
    for (int i = 0; i < 32; i += 8)
        t[tyy + i][txx] = in[(size_t)(by + tyy + i) * C + bx + txx];
    __syncthreads();
    #pragma unroll
    for (int i = 0; i < 32; i += 8)
        out[(size_t)(bx + tyy + i) * R + by + txx] = t[txx][tyy + i];
}

// ---------------------------------------------------------------------------
// concat: cat[:, NHID:] = target
// ---------------------------------------------------------------------------
__global__ void concat_copy(const float* __restrict__ target, float* __restrict__ cat)
{
    int idx = blockIdx.x * blockDim.x + threadIdx.x;     // float4 units
    if (idx >= NROWS * NFEAT / 4) return;
    int r = idx / (NFEAT / 4);
    int c4 = idx % (NFEAT / 4);
    *(float4*)(cat + (size_t)r * NCAT + NHID + c4 * 4) = ((const float4*)target)[idx];
}

// ---------------------------------------------------------------------------
// Row-wise log_softmax over NFEAT=512 columns, in place.
// ---------------------------------------------------------------------------
__global__ __launch_bounds__(256) void log_softmax_rows(float* __restrict__ io)
{
    const int row = blockIdx.x;
    float* x = io + (size_t)row * NFEAT;
    const int tid = threadIdx.x;
    __shared__ float red[8];

    float m = -INFINITY;
    for (int c = tid; c < NFEAT; c += 256) m = fmaxf(m, x[c]);
    #pragma unroll
    for (int o = 16; o; o >>= 1) m = fmaxf(m, __shfl_xor_sync(0xFFFFFFFFu, m, o));
    if ((tid & 31) == 0) red[tid >> 5] = m;
    __syncthreads();
    float rowmax = red[0];
    #pragma unroll
    for (int i = 1; i < 8; i++) rowmax = fmaxf(rowmax, red[i]);
    __syncthreads();

    float s = 0.0f;
    for (int c = tid; c < NFEAT; c += 256) s += expf(x[c] - rowmax);
    #pragma unroll
    for (int o = 16; o; o >>= 1) s += __shfl_xor_sync(0xFFFFFFFFu, s, o);
    if ((tid & 31) == 0) red[tid >> 5] = s;
    __syncthreads();
    float tot = 0.0f;
    #pragma unroll
    for (int i = 0; i < 8; i++) tot += red[i];
    const float lse = logf(tot) + rowmax;

    for (int c = tid; c < NFEAT; c += 256) x[c] = x[c] - lse;
}

// ---------------------------------------------------------------------------
// Launch
// ---------------------------------------------------------------------------
extern "C" void kernel_launch(void* const* d_in, const int* in_sizes, int n_in,
                              void* d_out, int out_size)
{
    const float* x      = (const float*)d_in[0];
    const float* target = (const float*)d_in[1];
    const float* adj0   = (const float*)d_in[2];
    const float* adj1   = (const float*)d_in[3];
    const float* gc1_w  = (const float*)d_in[4];
    const float* gc1_b  = (const float*)d_in[5];
    const float* gc2_w  = (const float*)d_in[6];
    const float* gc2_b  = (const float*)d_in[7];
    const float* lin1_w = (const float*)d_in[8];
    const float* lin1_b = (const float*)d_in[9];
    const float* lin2_w = (const float*)d_in[10];
    const float* lin2_b = (const float*)d_in[11];
    const float* lin3_w = (const float*)d_in[12];
    const float* lin3_b = (const float*)d_in[13];
    float* out = (float*)d_out;

    float *xw, *xwT, *h1, *h1w, *h1wT, *cat, *o4, *o5;
    float *w1T, *w2T, *l1T, *l2T, *l3T;
    cudaGetSymbolAddress((void**)&xw,   g_xw);
    cudaGetSymbolAddress((void**)&xwT,  g_xwT);
    cudaGetSymbolAddress((void**)&h1,   g_h1);
    cudaGetSymbolAddress((void**)&h1w,  g_h1w);
    cudaGetSymbolAddress((void**)&h1wT, g_h1wT);
    cudaGetSymbolAddress((void**)&cat,  g_cat);
    cudaGetSymbolAddress((void**)&o4,   g_o4);
    cudaGetSymbolAddress((void**)&o5,   g_o5);
    cudaGetSymbolAddress((void**)&w1T,  g_w1T);
    cudaGetSymbolAddress((void**)&w2T,  g_w2T);
    cudaGetSymbolAddress((void**)&l1T,  g_l1T);
    cudaGetSymbolAddress((void**)&l2T,  g_l2T);
    cudaGetSymbolAddress((void**)&l3T,  g_l3T);

    cudaFuncSetAttribute(tf32_gemm<false, false>,
                         cudaFuncAttributeMaxDynamicSharedMemorySize, DYN_SMEM);
    cudaFuncSetAttribute(tf32_gemm<true, true>,
                         cudaFuncAttributeMaxDynamicSharedMemorySize, DYN_SMEM);
    cudaFuncSetAttribute(tf32_gemm<false, true>,
                         cudaFuncAttributeMaxDynamicSharedMemorySize, DYN_SMEM);

    const dim3 tblk(32, 8);

    // Weight transposes ([K,N] -> [N,K])
    transpose_k<<<dim3(NHID / 32, NFEAT / 32), tblk>>>(gc1_w, w1T, NFEAT, NHID);
    transpose_k<<<dim3(NHID / 32, NHID / 32), tblk>>>(gc2_w, w2T, NHID, NHID);
    transpose_k<<<dim3(NCAT / 32, NCAT / 32), tblk>>>(lin1_w, l1T, NCAT, NCAT);
    transpose_k<<<dim3(NCAT / 32, NCAT / 32), tblk>>>(lin2_w, l2T, NCAT, NCAT);
    transpose_k<<<dim3(NFEAT / 32, NCAT / 32), tblk>>>(lin3_w, l3T, NCAT, NFEAT);

    // 1. xw = x @ gc1_w            [8192,512] @ [512,256]
    tf32_gemm<false, false><<<dim3(NHID / BN, NROWS / BM), 256, DYN_SMEM>>>(
        NFEAT, NHID, x, w1T, nullptr, xw);
    transpose_k<<<dim3(NHID / 32, NROWS / 32), tblk>>>(xw, xwT, NROWS, NHID);

    // 2. h1 = relu(adj0 @ xw + gc1_b)        [8192,8192] @ [8192,256]
    tf32_gemm<true, true><<<dim3(NHID / BN, NROWS / BM), 256, DYN_SMEM>>>(
        NROWS, NHID, adj0, xwT, gc1_b, h1);

    // 3. h1w = h1 @ gc2_w                    [8192,256] @ [256,256]
    tf32_gemm<false, false><<<dim3(NHID / BN, NROWS / BM), 256, DYN_SMEM>>>(
        NHID, NHID, h1, w2T, nullptr, h1w);
    transpose_k<<<dim3(NHID / 32, NROWS / 32), tblk>>>(h1w, h1wT, NROWS, NHID);

    // 4. cat[:, :256] = adj1 @ h1w + gc2_b   (ldc = 768)
    tf32_gemm<false, true><<<dim3(NHID / BN, NROWS / BM), 256, DYN_SMEM>>>(
        NROWS, NCAT, adj1, h1wT, gc2_b, cat);

    // 5. cat[:, 256:] = target_feats
    concat_copy<<<(NROWS * NFEAT / 4 + 255) / 256, 256>>>(target, cat);

    // 6. o4 = relu(cat @ lin1_w + lin1_b)    [8192,768] @ [768,768]
    tf32_gemm<true, true><<<dim3(NCAT / BN, NROWS / BM), 256, DYN_SMEM>>>(
        NCAT, NCAT, cat, l1T, lin1_b, o4);

    // 7. o5 = relu(o4 @ lin2_w + lin2_b)
    tf32_gemm<true, true><<<dim3(NCAT / BN, NROWS / BM), 256, DYN_SMEM>>>(
        NCAT, NCAT, o4, l2T, lin2_b, o5);

    // 8. out = o5 @ lin3_w + lin3_b          [8192,768] @ [768,512]
    tf32_gemm<false, true><<<dim3(NFEAT / BN, NROWS / BM), 256, DYN_SMEM>>>(
        NCAT, NFEAT, o5, l3T, lin3_b, out);

    // 9. log_softmax in place
    log_softmax_rows<<<NROWS, 256>>>(out);
}

// round 5
// speedup vs baseline: 4.7908x; 1.2657x over previous
#include <cuda_runtime.h>
#include <cuda_fp16.h>
#include <math.h>
#include <stdint.h>

// Problem dims (fixed per reference)
#define NROWS 8192
#define NFEAT 512
#define NHID  256
#define NCAT  768   // NHID + NFEAT

// ---------------------------------------------------------------------------
// Scratch (static device globals)
// ---------------------------------------------------------------------------
__device__ __half g_xw  [NROWS * NHID];
__device__ __half g_xwT [NHID * NROWS];
__device__ __half g_h1  [NROWS * NHID];
__device__ __half g_h1w [NROWS * NHID];
__device__ __half g_h1wT[NHID * NROWS];
__device__ __half g_cat [NROWS * NCAT];
__device__ __half g_o4  [NROWS * NCAT];
__device__ __half g_o5  [NROWS * NCAT];
__device__ __half g_w1T [NHID * NFEAT];
__device__ __half g_w2T [NHID * NHID];
__device__ __half g_l1T [NCAT * NCAT];
__device__ __half g_l2T [NCAT * NCAT];
__device__ __half g_l3T [NFEAT * NCAT];

// ---------------------------------------------------------------------------
// Helpers (baseline PTX only)
// ---------------------------------------------------------------------------
__device__ __forceinline__ uint32_t smem_u32(const void* p) {
    uint32_t a;
    asm("{ .reg .u64 t; cvta.to.shared.u64 t, %1; cvt.u32.u64 %0, t; }"
        : "=r"(a) : "l"(p));
    return a;
}
__device__ __forceinline__ void cpasync16(uint32_t dst, const void* src) {
    asm volatile("cp.async.cg.shared.global [%0], [%1], 16;" :: "r"(dst), "l"(src));
}
__device__ __forceinline__ void cp_commit() {
    asm volatile("cp.async.commit_group;" ::: "memory");
}
__device__ __forceinline__ void cp_wait3() {
    asm volatile("cp.async.wait_group 3;" ::: "memory");
}
__device__ __forceinline__ void cp_wait0() {
    asm volatile("cp.async.wait_group 0;" ::: "memory");
}
__device__ __forceinline__ void ldsm_x4(uint32_t* r, uint32_t addr) {
    asm volatile("ldmatrix.sync.aligned.m8n8.x4.shared.b16 {%0,%1,%2,%3}, [%4];"
                 : "=r"(r[0]), "=r"(r[1]), "=r"(r[2]), "=r"(r[3]) : "r"(addr));
}
__device__ __forceinline__ void ldsm_x2(uint32_t* r, uint32_t addr) {
    asm volatile("ldmatrix.sync.aligned.m8n8.x2.shared.b16 {%0,%1}, [%2];"
                 : "=r"(r[0]), "=r"(r[1]) : "r"(addr));
}
__device__ __forceinline__ void mma_f16(float* c, const uint32_t* a, const uint32_t* b) {
    asm volatile(
        "mma.sync.aligned.m16n8k16.row.col.f32.f16.f16.f32 "
        "{%0,%1,%2,%3}, {%4,%5,%6,%7}, {%8,%9}, {%0,%1,%2,%3};"
        : "+f"(c[0]), "+f"(c[1]), "+f"(c[2]), "+f"(c[3])
        : "r"(a[0]), "r"(a[1]), "r"(a[2]), "r"(a[3]), "r"(b[0]), "r"(b[1]));
}
__device__ __forceinline__ uint32_t h2u(__half2 h) { return *(uint32_t*)&h; }

// ---------------------------------------------------------------------------
// Tiling: BM=BN=128, BK=32, 256 threads (8 warps 2x4), warp tile 64x32.
// fp16 tile row = 32 halfs (64B) + 16B pad = 80B  -> conflict-free ldmatrix.
// fp32 staging row = 32 floats (128B) + 16B pad = 144B.
// ---------------------------------------------------------------------------
#define BM 128
#define BN 128
#define BK 32
#define ROWH 80
#define ROW32 144
#define H_TILE (BM * ROWH)          // 10240
#define A32_STAGE (BM * ROW32)      // 18432
// pure fp16 variant: 4-stage A16 + 4-stage B16
#define P_STAGE (2 * H_TILE)                    // 20480
#define DYN_P (4 * P_STAGE)                     // 81920
// convert variant: 4-stage A32 + 4-stage B16 + double A16
#define CV_B_OFF (4 * A32_STAGE)                // 73728
#define CV_A16_OFF (CV_B_OFF + 4 * H_TILE)      // 114688
#define DYN_CV (CV_A16_OFF + 2 * H_TILE)        // 135168

// half tile loader (A or B region): 128 rows x 64B = 512 chunks, 2/thread
__device__ __forceinline__ void load_h_tile(uint32_t base, int tid,
                                            const __half* rowp, int K, int k0) {
    #pragma unroll
    for (int i = 0; i < 2; i++) {
        const int c = tid + i * 256;
        const int row = c >> 2, q = c & 3;
        cpasync16(base + row * ROWH + q * 16,
                  rowp + (size_t)row * K + k0 + q * 8);
    }
}
// fp32 staging loader: 128 rows x 128B = 1024 chunks, 4/thread
__device__ __forceinline__ void load_f_tile(uint32_t base, int tid,
                                            const float* rowp, int K, int k0) {
    #pragma unroll
    for (int i = 0; i < 4; i++) {
        const int c = tid + i * 256;
        const int row = c >> 3, q = c & 7;
        cpasync16(base + row * ROW32 + q * 16,
                  rowp + (size_t)row * K + k0 + q * 4);
    }
}

// ---- shared mainloop body: ldsm + mma over one BK=32 tile ----
__device__ __forceinline__ void mma_tile(float acc[4][4][4],
                                         uint32_t aBase, uint32_t bBase) {
    #pragma unroll
    for (int ks = 0; ks < 2; ks++) {
        uint32_t af[4][4], bf[4][2];
        #pragma unroll
        for (int mt = 0; mt < 4; mt++)
            ldsm_x4(af[mt], aBase + mt * (16 * ROWH) + ks * 32);
        #pragma unroll
        for (int nt = 0; nt < 4; nt++)
            ldsm_x2(bf[nt], bBase + nt * (8 * ROWH) + ks * 32);
        #pragma unroll
        for (int mt = 0; mt < 4; mt++)
            #pragma unroll
            for (int nt = 0; nt < 4; nt++)
                mma_f16(acc[mt][nt], af[mt], bf[nt]);
    }
}

// ---- shared epilogue ----
template <bool RELU, bool BIAS, bool HALF_OUT>
__device__ __forceinline__ void epilogue(float acc[4][4][4], float scale,
                                         const float* bias, void* C, int ldc,
                                         int m0, int n0, int wm, int wn, int lane) {
    const int rbase = m0 + wm * 64 + (lane >> 2);
    const int cbase = n0 + wn * 32 + 2 * (lane & 3);
    #pragma unroll
    for (int mt = 0; mt < 4; mt++) {
        #pragma unroll
        for (int nt = 0; nt < 4; nt++) {
            const int col = cbase + nt * 8;
            float b0 = 0.0f, b1 = 0.0f;
            if (BIAS) { b0 = bias[col]; b1 = bias[col + 1]; }
            float v0 = acc[mt][nt][0] * scale + b0;
            float v1 = acc[mt][nt][1] * scale + b1;
            float v2 = acc[mt][nt][2] * scale + b0;
            float v3 = acc[mt][nt][3] * scale + b1;
            if (RELU) {
                v0 = fmaxf(v0, 0.0f); v1 = fmaxf(v1, 0.0f);
                v2 = fmaxf(v2, 0.0f); v3 = fmaxf(v3, 0.0f);
            }
            const int row = rbase + mt * 16;
            if (HALF_OUT) {
                __half* Ch = (__half*)C;
                *(__half2*)(Ch + (size_t)row * ldc + col)       = __floats2half2_rn(v0, v1);
                *(__half2*)(Ch + (size_t)(row + 8) * ldc + col) = __floats2half2_rn(v2, v3);
            } else {
                float* Cf = (float*)C;
                *(float2*)(Cf + (size_t)row * ldc + col)       = make_float2(v0, v1);
                *(float2*)(Cf + (size_t)(row + 8) * ldc + col) = make_float2(v2, v3);
            }
        }
    }
}

// ---------------------------------------------------------------------------
// Variant 1: pure fp16 GEMM.  C = A_h[M,K] @ Bt_h[N,K]^T * scale (+bias)(+relu)
// ---------------------------------------------------------------------------
template <bool RELU, bool BIAS, bool HALF_OUT>
__global__ __launch_bounds__(256, 2)
void h_gemm(int K, int ldc,
            const __half* __restrict__ A, const __half* __restrict__ Bt,
            const float* __restrict__ bias, void* __restrict__ C, float scale)
{
    extern __shared__ __align__(16) uint8_t dsraw[];
    const uint32_t smem = smem_u32(dsraw);
    const int tid = threadIdx.x, wid = tid >> 5, lane = tid & 31;
    const int wm = wid >> 2, wn = wid & 3;
    const int m0 = blockIdx.y * BM, n0 = blockIdx.x * BN;
    const int KT = K / BK;

    const __half* Arow = A + (size_t)m0 * K;
    const __half* Brow = Bt + (size_t)n0 * K;

    float acc[4][4][4];
    #pragma unroll
    for (int mt = 0; mt < 4; mt++)
        #pragma unroll
        for (int nt = 0; nt < 4; nt++)
            #pragma unroll
            for (int i = 0; i < 4; i++) acc[mt][nt][i] = 0.0f;

    const uint32_t aOff = (uint32_t)(wm * 64 + (lane & 15)) * ROWH + (lane >> 4) * 16;
    const uint32_t bOff = (uint32_t)(wn * 32 + (lane & 7)) * ROWH + ((lane >> 3) & 1) * 16;

    for (int tt = 0; tt < 3; tt++) {
        const uint32_t st = smem + (uint32_t)(tt & 3) * P_STAGE;
        load_h_tile(st, tid, Arow, K, tt * BK);
        load_h_tile(st + H_TILE, tid, Brow, K, tt * BK);
        cp_commit();
    }

    for (int t = 0; t < KT; t++) {
        __syncthreads();
        if (t + 3 < KT) {
            const uint32_t st = smem + (uint32_t)((t + 3) & 3) * P_STAGE;
            load_h_tile(st, tid, Arow, K, (t + 3) * BK);
            load_h_tile(st + H_TILE, tid, Brow, K, (t + 3) * BK);
        }
        cp_commit();
        cp_wait3();
        __syncthreads();
        const uint32_t st = smem + (uint32_t)(t & 3) * P_STAGE;
        mma_tile(acc, st + aOff, st + H_TILE + bOff);
    }
    cp_wait0();
    epilogue<RELU, BIAS, HALF_OUT>(acc, scale, bias, C, ldc, m0, n0, wm, wn, lane);
}

// ---------------------------------------------------------------------------
// Variant 2: fp32-A fused-convert GEMM.
// C = (alpha*A_f32)[M,K] @ Bt_h[N,K]^T * scale (+bias)(+relu)
// ---------------------------------------------------------------------------
template <bool RELU, bool BIAS, bool HALF_OUT>
__global__ __launch_bounds__(256, 1)
void h_gemm_cvt(int K, int ldc,
                const float* __restrict__ A, const __half* __restrict__ Bt,
                const float* __restrict__ bias, void* __restrict__ C,
                float alpha, float scale)
{
    extern __shared__ __align__(16) uint8_t dsraw[];
    const uint32_t smem = smem_u32(dsraw);
    uint8_t* dsm = dsraw;
    const int tid = threadIdx.x, wid = tid >> 5, lane = tid & 31;
    const int wm = wid >> 2, wn = wid & 3;
    const int m0 = blockIdx.y * BM, n0 = blockIdx.x * BN;
    const int KT = K / BK;

    const float* Arow = A + (size_t)m0 * K;
    const __half* Brow = Bt + (size_t)n0 * K;

    float acc[4][4][4];
    #pragma unroll
    for (int mt = 0; mt < 4; mt++)
        #pragma unroll
        for (int nt = 0; nt < 4; nt++)
            #pragma unroll
            for (int i = 0; i < 4; i++) acc[mt][nt][i] = 0.0f;

    const uint32_t aOff = (uint32_t)(wm * 64 + (lane & 15)) * ROWH + (lane >> 4) * 16;
    const uint32_t bOff = (uint32_t)(wn * 32 + (lane & 7)) * ROWH + ((lane >> 3) & 1) * 16;

    // convert-phase mapping: thread -> (row, half-row)
    const int crow = tid >> 1, chalf = tid & 1;

    for (int tt = 0; tt < 3; tt++) {
        load_f_tile(smem + (uint32_t)(tt & 3) * A32_STAGE, tid, Arow, K, tt * BK);
        load_h_tile(smem + CV_B_OFF + (uint32_t)(tt & 3) * H_TILE, tid, Brow, K, tt * BK);
        cp_commit();
    }

    for (int t = 0; t < KT; t++) {
        __syncthreads();                         // prev mma done; slots reusable
        if (t + 3 < KT) {
            load_f_tile(smem + (uint32_t)((t + 3) & 3) * A32_STAGE, tid, Arow, K, (t + 3) * BK);
            load_h_tile(smem + CV_B_OFF + (uint32_t)((t + 3) & 3) * H_TILE, tid, Brow, K, (t + 3) * BK);
        }
        cp_commit();
        cp_wait3();
        __syncthreads();                         // tile t visible to all

        // convert A32(t) -> A16(t&1), applying alpha
        {
            const uint8_t* s32 = dsm + (size_t)(t & 3) * A32_STAGE
                               + crow * ROW32 + chalf * 64;
            uint8_t* d16 = dsm + CV_A16_OFF + (size_t)(t & 1) * H_TILE
                         + crow * ROWH + chalf * 32;
            float4 f0 = ((const float4*)s32)[0];
            float4 f1 = ((const float4*)s32)[1];
            float4 f2 = ((const float4*)s32)[2];
            float4 f3 = ((const float4*)s32)[3];
            uint4 o0, o1;
            o0.x = h2u(__floats2half2_rn(f0.x * alpha, f0.y * alpha));
            o0.y = h2u(__floats2half2_rn(f0.z * alpha, f0.w * alpha));
            o0.z = h2u(__floats2half2_rn(f1.x * alpha, f1.y * alpha));
            o0.w = h2u(__floats2half2_rn(f1.z * alpha, f1.w * alpha));
            o1.x = h2u(__floats2half2_rn(f2.x * alpha, f2.y * alpha));
            o1.y = h2u(__floats2half2_rn(f2.z * alpha, f2.w * alpha));
            o1.z = h2u(__floats2half2_rn(f3.x * alpha, f3.y * alpha));
            o1.w = h2u(__floats2half2_rn(f3.z * alpha, f3.w * alpha));
            ((uint4*)d16)[0] = o0;
            ((uint4*)d16)[1] = o1;
        }
        __syncthreads();                         // A16(t) ready

        mma_tile(acc,
                 smem + CV_A16_OFF + (uint32_t)(t & 1) * H_TILE + aOff,
                 smem + CV_B_OFF + (uint32_t)(t & 3) * H_TILE + bOff);
    }
    cp_wait0();
    epilogue<RELU, BIAS, HALF_OUT>(acc, scale, bias, C, ldc, m0, n0, wm, wn, lane);
}

// ---------------------------------------------------------------------------
// fp32 -> fp16 transposed copy: out[C,R] = (half) in[R,C]^T
// ---------------------------------------------------------------------------
__global__ __launch_bounds__(256) void transpose_cvt(const float* __restrict__ in,
                                                     __half* __restrict__ out,
                                                     int R, int C)
{
    __shared__ float t[32][33];
    const int bx = blockIdx.x * 32, by = blockIdx.y * 32;
    const int tx = threadIdx.x, ty = threadIdx.y;
    #pragma unroll
    for (int i = 0; i < 32; i += 8)
        t[ty + i][tx] = in[(size_t)(by + ty + i) * C + bx + tx];
    __syncthreads();
    #pragma unroll
    for (int i = 0; i < 32; i += 8)
        out[(size_t)(bx + ty + i) * R + by + tx] = __float2half(t[tx][ty + i]);
}

// half -> half transpose
__global__ __launch_bounds__(256) void transpose_h(const __half* __restrict__ in,
                                                   __half* __restrict__ out,
                                                   int R, int C)
{
    __shared__ __half t[32][34];
    const int bx = blockIdx.x * 32, by = blockIdx.y * 32;
    const int tx = threadIdx.x, ty = threadIdx.y;
    #pragma unroll
    for (int i = 0; i < 32; i += 8)
        t[ty + i][tx] = in[(size_t)(by + ty + i) * C + bx + tx];
    __syncthreads();
    #pragma unroll
    for (int i = 0; i < 32; i += 8)
        out[(size_t)(bx + ty + i) * R + by + tx] = t[tx][ty + i];
}

// concat: cat[:, NHID:] = (half) target
__global__ void concat_h(const float* __restrict__ target, __half* __restrict__ cat)
{
    int idx = blockIdx.x * blockDim.x + threadIdx.x;       // half2 units
    if (idx >= NROWS * NFEAT / 2) return;
    int r = idx / (NFEAT / 2);
    int c2 = idx % (NFEAT / 2);
    float2 v = ((const float2*)target)[idx];
    *(__half2*)(cat + (size_t)r * NCAT + NHID + c2 * 2) = __floats2half2_rn(v.x, v.y);
}

// ---------------------------------------------------------------------------
// Row-wise log_softmax over NFEAT=512 columns, in place (fp32).
// ---------------------------------------------------------------------------
__global__ __launch_bounds__(256) void log_softmax_rows(float* __restrict__ io)
{
    const int row = blockIdx.x;
    float* x = io + (size_t)row * NFEAT;
    const int tid = threadIdx.x;
    __shared__ float red[8];

    float m = -INFINITY;
    for (int c = tid; c < NFEAT; c += 256) m = fmaxf(m, x[c]);
    #pragma unroll
    for (int o = 16; o; o >>= 1) m = fmaxf(m, __shfl_xor_sync(0xFFFFFFFFu, m, o));
    if ((tid & 31) == 0) red[tid >> 5] = m;
    __syncthreads();
    float rowmax = red[0];
    #pragma unroll
    for (int i = 1; i < 8; i++) rowmax = fmaxf(rowmax, red[i]);
    __syncthreads();

    float s = 0.0f;
    for (int c = tid; c < NFEAT; c += 256) s += expf(x[c] - rowmax);
    #pragma unroll
    for (int o = 16; o; o >>= 1) s += __shfl_xor_sync(0xFFFFFFFFu, s, o);
    if ((tid & 31) == 0) red[tid >> 5] = s;
    __syncthreads();
    float tot = 0.0f;
    #pragma unroll
    for (int i = 0; i < 8; i++) tot += red[i];
    const float lse = logf(tot) + rowmax;

    for (int c = tid; c < NFEAT; c += 256) x[c] = x[c] - lse;
}

// ---------------------------------------------------------------------------
// Launch
// ---------------------------------------------------------------------------
#define ADJ_SCALE 8192.0f
#define ADJ_INV   (1.0f / 8192.0f)

extern "C" void kernel_launch(void* const* d_in, const int* in_sizes, int n_in,
                              void* d_out, int out_size)
{
    const float* x      = (const float*)d_in[0];
    const float* target = (const float*)d_in[1];
    const float* adj0   = (const float*)d_in[2];
    const float* adj1   = (const float*)d_in[3];
    const float* gc1_w  = (const float*)d_in[4];
    const float* gc1_b  = (const float*)d_in[5];
    const float* gc2_w  = (const float*)d_in[6];
    const float* gc2_b  = (const float*)d_in[7];
    const float* lin1_w = (const float*)d_in[8];
    const float* lin1_b = (const float*)d_in[9];
    const float* lin2_w = (const float*)d_in[10];
    const float* lin2_b = (const float*)d_in[11];
    const float* lin3_w = (const float*)d_in[12];
    const float* lin3_b = (const float*)d_in[13];
    float* out = (float*)d_out;

    __half *xw, *xwT, *h1, *h1w, *h1wT, *cat, *o4, *o5;
    __half *w1T, *w2T, *l1T, *l2T, *l3T;
    cudaGetSymbolAddress((void**)&xw,   g_xw);
    cudaGetSymbolAddress((void**)&xwT,  g_xwT);
    cudaGetSymbolAddress((void**)&h1,   g_h1);
    cudaGetSymbolAddress((void**)&h1w,  g_h1w);
    cudaGetSymbolAddress((void**)&h1wT, g_h1wT);
    cudaGetSymbolAddress((void**)&cat,  g_cat);
    cudaGetSymbolAddress((void**)&o4,   g_o4);
    cudaGetSymbolAddress((void**)&o5,   g_o5);
    cudaGetSymbolAddress((void**)&w1T,  g_w1T);
    cudaGetSymbolAddress((void**)&w2T,  g_w2T);
    cudaGetSymbolAddress((void**)&l1T,  g_l1T);
    cudaGetSymbolAddress((void**)&l2T,  g_l2T);
    cudaGetSymbolAddress((void**)&l3T,  g_l3T);

    // raise dynamic smem limits
    cudaFuncSetAttribute(h_gemm<false, false, true>,  cudaFuncAttributeMaxDynamicSharedMemorySize, DYN_P);
    cudaFuncSetAttribute(h_gemm<true,  true,  true>,  cudaFuncAttributeMaxDynamicSharedMemorySize, DYN_P);
    cudaFuncSetAttribute(h_gemm<false, true,  false>, cudaFuncAttributeMaxDynamicSharedMemorySize, DYN_P);
    cudaFuncSetAttribute(h_gemm_cvt<false, false, true>, cudaFuncAttributeMaxDynamicSharedMemorySize, DYN_CV);
    cudaFuncSetAttribute(h_gemm_cvt<true,  true,  true>, cudaFuncAttributeMaxDynamicSharedMemorySize, DYN_CV);
    cudaFuncSetAttribute(h_gemm_cvt<false, true,  true>, cudaFuncAttributeMaxDynamicSharedMemorySize, DYN_CV);

    const dim3 tblk(32, 8);

    // Weight transposes + fp16 convert ([K,N] -> [N,K] half)
    transpose_cvt<<<dim3(NHID / 32, NFEAT / 32), tblk>>>(gc1_w, w1T, NFEAT, NHID);
    transpose_cvt<<<dim3(NHID / 32, NHID / 32), tblk>>>(gc2_w, w2T, NHID, NHID);
    transpose_cvt<<<dim3(NCAT / 32, NCAT / 32), tblk>>>(lin1_w, l1T, NCAT, NCAT);
    transpose_cvt<<<dim3(NCAT / 32, NCAT / 32), tblk>>>(lin2_w, l2T, NCAT, NCAT);
    transpose_cvt<<<dim3(NFEAT / 32, NCAT / 32), tblk>>>(lin3_w, l3T, NCAT, NFEAT);

    // 1. xw = x @ gc1_w    (fp32 A fused-convert, alpha=1)
    h_gemm_cvt<false, false, true><<<dim3(NHID / BN, NROWS / BM), 256, DYN_CV>>>(
        NFEAT, NHID, x, w1T, nullptr, xw, 1.0f, 1.0f);
    transpose_h<<<dim3(NHID / 32, NROWS / 32), tblk>>>(xw, xwT, NROWS, NHID);

    // 2. h1 = relu(adj0 @ xw + gc1_b)   (adj scaled 2^13, epilogue 2^-13)
    h_gemm_cvt<true, true, true><<<dim3(NHID / BN, NROWS / BM), 256, DYN_CV>>>(
        NROWS, NHID, adj0, xwT, gc1_b, h1, ADJ_SCALE, ADJ_INV);

    // 3. h1w = h1 @ gc2_w  (pure fp16)
    h_gemm<false, false, true><<<dim3(NHID / BN, NROWS / BM), 256, DYN_P>>>(
        NHID, NHID, h1, w2T, nullptr, h1w, 1.0f);
    transpose_h<<<dim3(NHID / 32, NROWS / 32), tblk>>>(h1w, h1wT, NROWS, NHID);

    // 4. cat[:, :256] = adj1 @ h1w + gc2_b   (ldc = 768)
    h_gemm_cvt<false, true, true><<<dim3(NHID / BN, NROWS / BM), 256, DYN_CV>>>(
        NROWS, NCAT, adj1, h1wT, gc2_b, cat, ADJ_SCALE, ADJ_INV);

    // 5. cat[:, 256:] = target_feats
    concat_h<<<(NROWS * NFEAT / 2 + 255) / 256, 256>>>(target, cat);

    // 6. o4 = relu(cat @ lin1_w + lin1_b)
    h_gemm<true, true, true><<<dim3(NCAT / BN, NROWS / BM), 256, DYN_P>>>(
        NCAT, NCAT, cat, l1T, lin1_b, o4, 1.0f);

    // 7. o5 = relu(o4 @ lin2_w + lin2_b)
    h_gemm<true, true, true><<<dim3(NCAT / BN, NROWS / BM), 256, DYN_P>>>(
        NCAT, NCAT, o4, l2T, lin2_b, o5, 1.0f);

    // 8. out = o5 @ lin3_w + lin3_b   (fp32 out)
    h_gemm<false, true, false><<<dim3(NFEAT / BN, NROWS / BM), 256, DYN_P>>>(
        NCAT, NFEAT, o5, l3T, lin3_b, out, 1.0f);

    // 9. log_softmax in place
    log_softmax_rows<<<NROWS, 256>>>(out);
}

// round 6
// speedup vs baseline: 5.3502x; 1.1168x over previous
#include <cuda_runtime.h>
#include <cuda_fp16.h>
#include <math.h>
#include <stdint.h>

// Problem dims (fixed per reference)
#define NROWS 8192
#define NFEAT 512
#define NHID  256
#define NCAT  768   // NHID + NFEAT

// ---------------------------------------------------------------------------
// Scratch (static device globals)
// ---------------------------------------------------------------------------
__device__ __half g_xwT [NHID * NROWS];
__device__ __half g_h1  [NROWS * NHID];
__device__ __half g_h1wT[NHID * NROWS];
__device__ __half g_cat [NROWS * NCAT];
__device__ __half g_o4  [NROWS * NCAT];
__device__ __half g_o5  [NROWS * NCAT];
__device__ __half g_w1T [NHID * NFEAT];
__device__ __half g_w2T [NHID * NHID];
__device__ __half g_l1T [NCAT * NCAT];
__device__ __half g_l2T [NCAT * NCAT];
__device__ __half g_l3T [NFEAT * NCAT];

// ---------------------------------------------------------------------------
// Helpers (baseline PTX only)
// ---------------------------------------------------------------------------
__device__ __forceinline__ uint32_t smem_u32(const void* p) {
    uint32_t a;
    asm("{ .reg .u64 t; cvta.to.shared.u64 t, %1; cvt.u32.u64 %0, t; }"
        : "=r"(a) : "l"(p));
    return a;
}
__device__ __forceinline__ void cpasync16(uint32_t dst, const void* src) {
    asm volatile("cp.async.cg.shared.global [%0], [%1], 16;" :: "r"(dst), "l"(src));
}
__device__ __forceinline__ void cp_commit() {
    asm volatile("cp.async.commit_group;" ::: "memory");
}
__device__ __forceinline__ void cp_wait2() {
    asm volatile("cp.async.wait_group 2;" ::: "memory");
}
__device__ __forceinline__ void cp_wait0() {
    asm volatile("cp.async.wait_group 0;" ::: "memory");
}
__device__ __forceinline__ void ldsm_x4(uint32_t* r, uint32_t addr) {
    asm volatile("ldmatrix.sync.aligned.m8n8.x4.shared.b16 {%0,%1,%2,%3}, [%4];"
                 : "=r"(r[0]), "=r"(r[1]), "=r"(r[2]), "=r"(r[3]) : "r"(addr));
}
__device__ __forceinline__ void mma_f16(float* c, const uint32_t* a, const uint32_t* b) {
    asm volatile(
        "mma.sync.aligned.m16n8k16.row.col.f32.f16.f16.f32 "
        "{%0,%1,%2,%3}, {%4,%5,%6,%7}, {%8,%9}, {%0,%1,%2,%3};"
        : "+f"(c[0]), "+f"(c[1]), "+f"(c[2]), "+f"(c[3])
        : "r"(a[0]), "r"(a[1]), "r"(a[2]), "r"(a[3]), "r"(b[0]), "r"(b[1]));
}
__device__ __forceinline__ uint32_t h2u(__half2 h) { return *(uint32_t*)&h; }

// ---------------------------------------------------------------------------
// Tiling: BM=BN=128, BK=32, 256 threads (8 warps 2x4), warp tile 64x32.
// fp16 tile row = 32 halfs (64B) + 16B pad = 80B  -> conflict-free ldmatrix.
// ---------------------------------------------------------------------------
#define BM 128
#define BN 128
#define BK 32
#define ROWH 80
#define H_TILE (BM * ROWH)          // 10240
// pure fp16 kernel: 4-stage {A16,B16}
#define P_STAGE (2 * H_TILE)        // 20480
#define DYN_P (4 * P_STAGE)         // 81920  -> occupancy 2
// convert kernel: 2-stage A16 + 4-stage B16
#define HC_B_OFF (2 * H_TILE)       // 20480
#define DYN_HC (6 * H_TILE)         // 61440  -> occupancy 2

// half tile loader: 128 rows x 64B = 512 chunks, 2/thread
__device__ __forceinline__ void load_h_tile(uint32_t base, int tid,
                                            const __half* rowp, int K, int k0) {
    #pragma unroll
    for (int i = 0; i < 2; i++) {
        const int c = tid + i * 256;
        const int row = c >> 2, q = c & 3;
        cpasync16(base + row * ROWH + q * 16,
                  rowp + (size_t)row * K + k0 + q * 8);
    }
}

// A-fp32: 16 consecutive floats per thread (4x LDG.128)
__device__ __forceinline__ void ldg16(float* ar, const float* p) {
    float4 v0 = ((const float4*)p)[0];
    float4 v1 = ((const float4*)p)[1];
    float4 v2 = ((const float4*)p)[2];
    float4 v3 = ((const float4*)p)[3];
    ar[0]  = v0.x; ar[1]  = v0.y; ar[2]  = v0.z; ar[3]  = v0.w;
    ar[4]  = v1.x; ar[5]  = v1.y; ar[6]  = v1.z; ar[7]  = v1.w;
    ar[8]  = v2.x; ar[9]  = v2.y; ar[10] = v2.z; ar[11] = v2.w;
    ar[12] = v3.x; ar[13] = v3.y; ar[14] = v3.z; ar[15] = v3.w;
}
// convert 16 floats * alpha -> 16 halfs -> 2x STS.128
__device__ __forceinline__ void cvt_sts(const float* ar, uint32_t dst, float alpha) {
    uint32_t o[8];
    #pragma unroll
    for (int i = 0; i < 8; i++)
        o[i] = h2u(__floats2half2_rn(ar[2 * i] * alpha, ar[2 * i + 1] * alpha));
    asm volatile("st.shared.v4.b32 [%0], {%1,%2,%3,%4};"
                 :: "r"(dst), "r"(o[0]), "r"(o[1]), "r"(o[2]), "r"(o[3]));
    asm volatile("st.shared.v4.b32 [%0], {%1,%2,%3,%4};"
                 :: "r"(dst + 16), "r"(o[4]), "r"(o[5]), "r"(o[6]), "r"(o[7]));
}

// ---- mainloop body: ldsm + mma over one BK=32 tile (B via x4: 2 nt/ldsm) ----
__device__ __forceinline__ void mma_tile(float acc[4][4][4],
                                         uint32_t aBase, uint32_t bBase4) {
    #pragma unroll
    for (int ks = 0; ks < 2; ks++) {
        uint32_t af[4][4], bf[4][2];
        #pragma unroll
        for (int mt = 0; mt < 4; mt++)
            ldsm_x4(af[mt], aBase + mt * (16 * ROWH) + ks * 32);
        #pragma unroll
        for (int p = 0; p < 2; p++) {
            uint32_t q[4];
            ldsm_x4(q, bBase4 + p * (16 * ROWH) + ks * 32);
            bf[2 * p][0] = q[0]; bf[2 * p][1] = q[1];
            bf[2 * p + 1][0] = q[2]; bf[2 * p + 1][1] = q[3];
        }
        #pragma unroll
        for (int mt = 0; mt < 4; mt++)
            #pragma unroll
            for (int nt = 0; nt < 4; nt++)
                mma_f16(acc[mt][nt], af[mt], bf[nt]);
    }
}

// ---- epilogue: normal (direct) or transposed (smem-staged) ----
template <bool RELU, bool BIAS, bool HALF_OUT, bool TRANS>
__device__ __forceinline__ void epilogue(float acc[4][4][4], float scale,
                                         const float* bias, void* C, int ldc,
                                         int m0, int n0, int wm, int wn,
                                         int lane, int wid, uint8_t* scratch) {
    if (!TRANS) {
        const int rbase = m0 + wm * 64 + (lane >> 2);
        const int cbase = n0 + wn * 32 + 2 * (lane & 3);
        #pragma unroll
        for (int mt = 0; mt < 4; mt++) {
            #pragma unroll
            for (int nt = 0; nt < 4; nt++) {
                const int col = cbase + nt * 8;
                float b0 = 0.0f, b1 = 0.0f;
                if (BIAS) { b0 = bias[col]; b1 = bias[col + 1]; }
                float v0 = acc[mt][nt][0] * scale + b0;
                float v1 = acc[mt][nt][1] * scale + b1;
                float v2 = acc[mt][nt][2] * scale + b0;
                float v3 = acc[mt][nt][3] * scale + b1;
                if (RELU) {
                    v0 = fmaxf(v0, 0.0f); v1 = fmaxf(v1, 0.0f);
                    v2 = fmaxf(v2, 0.0f); v3 = fmaxf(v3, 0.0f);
                }
                const int row = rbase + mt * 16;
                if (HALF_OUT) {
                    __half* Ch = (__half*)C;
                    *(__half2*)(Ch + (size_t)row * ldc + col)       = __floats2half2_rn(v0, v1);
                    *(__half2*)(Ch + (size_t)(row + 8) * ldc + col) = __floats2half2_rn(v2, v3);
                } else {
                    float* Cf = (float*)C;
                    *(float2*)(Cf + (size_t)row * ldc + col)       = make_float2(v0, v1);
                    *(float2*)(Cf + (size_t)(row + 8) * ldc + col) = make_float2(v2, v3);
                }
            }
        }
    } else {
        // C^T output (half only, no bias/relu; scale applied).
        // Per-warp 32(cols) x 64(rows) scratch tile, row stride 72 halfs.
        __half* sw = (__half*)scratch + (size_t)wid * (32 * 72);
        #pragma unroll
        for (int mt = 0; mt < 4; mt++) {
            #pragma unroll
            for (int nt = 0; nt < 4; nt++) {
                const int r = (lane >> 2) + mt * 16;
                const int c = 2 * (lane & 3) + nt * 8;
                sw[(size_t)c * 72 + r]           = __float2half(acc[mt][nt][0] * scale);
                sw[(size_t)(c + 1) * 72 + r]     = __float2half(acc[mt][nt][1] * scale);
                sw[(size_t)c * 72 + r + 8]       = __float2half(acc[mt][nt][2] * scale);
                sw[(size_t)(c + 1) * 72 + r + 8] = __float2half(acc[mt][nt][3] * scale);
            }
        }
        __syncwarp();
        __half* dst = (__half*)C + (size_t)(n0 + wn * 32 + lane) * ldc + m0 + wm * 64;
        const uint4* srow = (const uint4*)(sw + (size_t)lane * 72);
        uint4* d4 = (uint4*)dst;
        #pragma unroll
        for (int i = 0; i < 8; i++) d4[i] = srow[i];
    }
}

// ---------------------------------------------------------------------------
// Pure fp16 GEMM: C = A_h[M,K] @ Bt_h[N,K]^T * scale (+bias)(+relu)
// One __syncthreads per iteration (shifted cp.async wait).
// ---------------------------------------------------------------------------
template <bool RELU, bool BIAS, bool HALF_OUT, bool TRANS>
__global__ __launch_bounds__(256, 2)
void h_gemm(int K, int ldc,
            const __half* __restrict__ A, const __half* __restrict__ Bt,
            const float* __restrict__ bias, void* __restrict__ C, float scale)
{
    extern __shared__ __align__(16) uint8_t dsraw[];
    const uint32_t smem = smem_u32(dsraw);
    const int tid = threadIdx.x, wid = tid >> 5, lane = tid & 31;
    const int wm = wid >> 2, wn = wid & 3;
    const int m0 = blockIdx.y * BM, n0 = blockIdx.x * BN;
    const int KT = K / BK;

    const __half* Arow = A + (size_t)m0 * K;
    const __half* Brow = Bt + (size_t)n0 * K;

    float acc[4][4][4];
    #pragma unroll
    for (int mt = 0; mt < 4; mt++)
        #pragma unroll
        for (int nt = 0; nt < 4; nt++)
            #pragma unroll
            for (int i = 0; i < 4; i++) acc[mt][nt][i] = 0.0f;

    const uint32_t aOff = (uint32_t)(wm * 64 + (lane & 15)) * ROWH + (lane >> 4) * 16;
    const uint32_t bOff4 = (uint32_t)(wn * 32 + (lane & 7) + ((lane >> 4) & 1) * 8) * ROWH
                         + ((lane >> 3) & 1) * 16;

    #pragma unroll
    for (int tt = 0; tt < 3; tt++) {
        const uint32_t st = smem + (uint32_t)tt * P_STAGE;
        load_h_tile(st, tid, Arow, K, tt * BK);
        load_h_tile(st + H_TILE, tid, Brow, K, tt * BK);
        cp_commit();
    }
    cp_wait2();                                    // tile 0 landed (this thread)

    for (int t = 0; t < KT; t++) {
        __syncthreads();                           // publish tile t (+ free stage (t-1)&3)
        if (t + 3 < KT) {
            const uint32_t st = smem + (uint32_t)((t + 3) & 3) * P_STAGE;
            load_h_tile(st, tid, Arow, K, (t + 3) * BK);
            load_h_tile(st + H_TILE, tid, Brow, K, (t + 3) * BK);
        }
        cp_commit();
        const uint32_t st = smem + (uint32_t)(t & 3) * P_STAGE;
        mma_tile(acc, st + aOff, st + H_TILE + bOff4);
        cp_wait2();                                // tile t+1 landed (this thread)
    }
    cp_wait0();
    __syncthreads();                               // smem reusable as scratch
    epilogue<RELU, BIAS, HALF_OUT, TRANS>(acc, scale, bias, C, ldc,
                                          m0, n0, wm, wn, lane, wid, dsraw);
}

// ---------------------------------------------------------------------------
// fp32-A fused-convert GEMM: C = (alpha*A_f32) @ Bt_h^T * scale (+bias)(+relu)
// A loaded LDG->regs one tile ahead, converted into a 2-stage fp16 ring.
// One __syncthreads per iteration.  Occupancy 2.
// ---------------------------------------------------------------------------
template <bool RELU, bool BIAS, bool HALF_OUT, bool TRANS>
__global__ __launch_bounds__(256, 2)
void hc_gemm(int K, int ldc,
             const float* __restrict__ A, const __half* __restrict__ Bt,
             const float* __restrict__ bias, void* __restrict__ C,
             float alpha, float scale)
{
    extern __shared__ __align__(16) uint8_t dsraw[];
    const uint32_t smem = smem_u32(dsraw);
    const int tid = threadIdx.x, wid = tid >> 5, lane = tid & 31;
    const int wm = wid >> 2, wn = wid & 3;
    const int m0 = blockIdx.y * BM, n0 = blockIdx.x * BN;
    const int KT = K / BK;

    const float* Arow = A + (size_t)m0 * K;
    const __half* Brow = Bt + (size_t)n0 * K;

    float acc[4][4][4];
    #pragma unroll
    for (int mt = 0; mt < 4; mt++)
        #pragma unroll
        for (int nt = 0; nt < 4; nt++)
            #pragma unroll
            for (int i = 0; i < 4; i++) acc[mt][nt][i] = 0.0f;

    const uint32_t aOff = (uint32_t)(wm * 64 + (lane & 15)) * ROWH + (lane >> 4) * 16;
    const uint32_t bOff4 = (uint32_t)(wn * 32 + (lane & 7) + ((lane >> 4) & 1) * 8) * ROWH
                         + ((lane >> 3) & 1) * 16;

    // convert mapping: thread -> (row, 16-float half-row)
    const int crow = tid >> 1, chalf = tid & 1;
    const float* aptr0 = Arow + (size_t)crow * K + chalf * 16;
    const uint32_t cvtDstBase = smem + crow * ROWH + chalf * 32;

    float ar[16];
    // prologue
    ldg16(ar, aptr0);                                        // tile 0 -> regs
    load_h_tile(smem + HC_B_OFF, tid, Brow, K, 0);  cp_commit();
    load_h_tile(smem + HC_B_OFF + H_TILE, tid, Brow, K, BK); cp_commit();
    load_h_tile(smem + HC_B_OFF + 2 * H_TILE, tid, Brow, K, 2 * BK); cp_commit();
    cvt_sts(ar, cvtDstBase, alpha);                          // tile 0 -> A16[0]
    if (KT > 1) ldg16(ar, aptr0 + BK);                       // tile 1 -> regs
    cp_wait2();                                              // B0 landed (this thread)

    for (int t = 0; t < KT; t++) {
        __syncthreads();             // publish A16[t&1] + B tile t; free A16[(t+1)&1]
        if (t + 1 < KT)
            cvt_sts(ar, cvtDstBase + (uint32_t)((t + 1) & 1) * H_TILE, alpha);
        if (t + 2 < KT)
            ldg16(ar, aptr0 + (size_t)(t + 2) * BK);
        if (t + 3 < KT)
            load_h_tile(smem + HC_B_OFF + (uint32_t)((t + 3) & 3) * H_TILE,
                        tid, Brow, K, (t + 3) * BK);
        cp_commit();
        mma_tile(acc, smem + (uint32_t)(t & 1) * H_TILE + aOff,
                 smem + HC_B_OFF + (uint32_t)(t & 3) * H_TILE + bOff4);
        cp_wait2();                  // B tile t+1 landed (this thread)
    }
    cp_wait0();
    __syncthreads();
    epilogue<RELU, BIAS, HALF_OUT, TRANS>(acc, scale, bias, C, ldc,
                                          m0, n0, wm, wn, lane, wid, dsraw);
}

// ---------------------------------------------------------------------------
// fp32 -> fp16 transposed copy (weights): out[C,R] = (half) in[R,C]^T
// ---------------------------------------------------------------------------
__global__ __launch_bounds__(256) void transpose_cvt(const float* __restrict__ in,
                                                     __half* __restrict__ out,
                                                     int R, int C)
{
    __shared__ float t[32][33];
    const int bx = blockIdx.x * 32, by = blockIdx.y * 32;
    const int tx = threadIdx.x, ty = threadIdx.y;
    #pragma unroll
    for (int i = 0; i < 32; i += 8)
        t[ty + i][tx] = in[(size_t)(by + ty + i) * C + bx + tx];
    __syncthreads();
    #pragma unroll
    for (int i = 0; i < 32; i += 8)
        out[(size_t)(bx + ty + i) * R + by + tx] = __float2half(t[tx][ty + i]);
}

// concat: cat[:, NHID:] = (half) target
__global__ void concat_h(const float* __restrict__ target, __half* __restrict__ cat)
{
    int idx = blockIdx.x * blockDim.x + threadIdx.x;       // half2 units
    if (idx >= NROWS * NFEAT / 2) return;
    int r = idx / (NFEAT / 2);
    int c2 = idx % (NFEAT / 2);
    float2 v = ((const float2*)target)[idx];
    *(__half2*)(cat + (size_t)r * NCAT + NHID + c2 * 2) = __floats2half2_rn(v.x, v.y);
}

// ---------------------------------------------------------------------------
// Row-wise log_softmax over NFEAT=512 columns, in place (fp32).
// ---------------------------------------------------------------------------
__global__ __launch_bounds__(256) void log_softmax_rows(float* __restrict__ io)
{
    const int row = blockIdx.x;
    float* x = io + (size_t)row * NFEAT;
    const int tid = threadIdx.x;
    __shared__ float red[8];

    float m = -INFINITY;
    for (int c = tid; c < NFEAT; c += 256) m = fmaxf(m, x[c]);
    #pragma unroll
    for (int o = 16; o; o >>= 1) m = fmaxf(m, __shfl_xor_sync(0xFFFFFFFFu, m, o));
    if ((tid & 31) == 0) red[tid >> 5] = m;
    __syncthreads();
    float rowmax = red[0];
    #pragma unroll
    for (int i = 1; i < 8; i++) rowmax = fmaxf(rowmax, red[i]);
    __syncthreads();

    float s = 0.0f;
    for (int c = tid; c < NFEAT; c += 256) s += expf(x[c] - rowmax);
    #pragma unroll
    for (int o = 16; o; o >>= 1) s += __shfl_xor_sync(0xFFFFFFFFu, s, o);
    if ((tid & 31) == 0) red[tid >> 5] = s;
    __syncthreads();
    float tot = 0.0f;
    #pragma unroll
    for (int i = 0; i < 8; i++) tot += red[i];
    const float lse = logf(tot) + rowmax;

    for (int c = tid; c < NFEAT; c += 256) x[c] = x[c] - lse;
}

// ---------------------------------------------------------------------------
// Launch
// ---------------------------------------------------------------------------
#define ADJ_SCALE 8192.0f
#define ADJ_INV   (1.0f / 8192.0f)

extern "C" void kernel_launch(void* const* d_in, const int* in_sizes, int n_in,
                              void* d_out, int out_size)
{
    const float* x      = (const float*)d_in[0];
    const float* target = (const float*)d_in[1];
    const float* adj0   = (const float*)d_in[2];
    const float* adj1   = (const float*)d_in[3];
    const float* gc1_w  = (const float*)d_in[4];
    const float* gc1_b  = (const float*)d_in[5];
    const float* gc2_w  = (const float*)d_in[6];
    const float* gc2_b  = (const float*)d_in[7];
    const float* lin1_w = (const float*)d_in[8];
    const float* lin1_b = (const float*)d_in[9];
    const float* lin2_w = (const float*)d_in[10];
    const float* lin2_b = (const float*)d_in[11];
    const float* lin3_w = (const float*)d_in[12];
    const float* lin3_b = (const float*)d_in[13];
    float* out = (float*)d_out;

    __half *xwT, *h1, *h1wT, *cat, *o4, *o5;
    __half *w1T, *w2T, *l1T, *l2T, *l3T;
    cudaGetSymbolAddress((void**)&xwT,  g_xwT);
    cudaGetSymbolAddress((void**)&h1,   g_h1);
    cudaGetSymbolAddress((void**)&h1wT, g_h1wT);
    cudaGetSymbolAddress((void**)&cat,  g_cat);
    cudaGetSymbolAddress((void**)&o4,   g_o4);
    cudaGetSymbolAddress((void**)&o5,   g_o5);
    cudaGetSymbolAddress((void**)&w1T,  g_w1T);
    cudaGetSymbolAddress((void**)&w2T,  g_w2T);
    cudaGetSymbolAddress((void**)&l1T,  g_l1T);
    cudaGetSymbolAddress((void**)&l2T,  g_l2T);
    cudaGetSymbolAddress((void**)&l3T,  g_l3T);

    cudaFuncSetAttribute(h_gemm<false, false, true, true>,  cudaFuncAttributeMaxDynamicSharedMemorySize, DYN_P);
    cudaFuncSetAttribute(h_gemm<true,  true,  true, false>, cudaFuncAttributeMaxDynamicSharedMemorySize, DYN_P);
    cudaFuncSetAttribute(h_gemm<false, true,  false, false>, cudaFuncAttributeMaxDynamicSharedMemorySize, DYN_P);
    cudaFuncSetAttribute(hc_gemm<false, false, true, true>,  cudaFuncAttributeMaxDynamicSharedMemorySize, DYN_HC);
    cudaFuncSetAttribute(hc_gemm<true,  true,  true, false>, cudaFuncAttributeMaxDynamicSharedMemorySize, DYN_HC);
    cudaFuncSetAttribute(hc_gemm<false, true,  true, false>, cudaFuncAttributeMaxDynamicSharedMemorySize, DYN_HC);

    const dim3 tblk(32, 8);

    // Weight transposes + fp16 convert ([K,N] -> [N,K] half)
    transpose_cvt<<<dim3(NHID / 32, NFEAT / 32), tblk>>>(gc1_w, w1T, NFEAT, NHID);
    transpose_cvt<<<dim3(NHID / 32, NHID / 32), tblk>>>(gc2_w, w2T, NHID, NHID);
    transpose_cvt<<<dim3(NCAT / 32, NCAT / 32), tblk>>>(lin1_w, l1T, NCAT, NCAT);
    transpose_cvt<<<dim3(NCAT / 32, NCAT / 32), tblk>>>(lin2_w, l2T, NCAT, NCAT);
    transpose_cvt<<<dim3(NFEAT / 32, NCAT / 32), tblk>>>(lin3_w, l3T, NCAT, NFEAT);

    // 1. xwT = (x @ gc1_w)^T   (fp32 A, transposed epilogue, ldc = NROWS)
    hc_gemm<false, false, true, true><<<dim3(NHID / BN, NROWS / BM), 256, DYN_HC>>>(
        NFEAT, NROWS, x, w1T, nullptr, xwT, 1.0f, 1.0f);

    // 2. h1 = relu(adj0 @ xw + gc1_b)   (adj scaled 2^13, epilogue 2^-13)
    hc_gemm<true, true, true, false><<<dim3(NHID / BN, NROWS / BM), 256, DYN_HC>>>(
        NROWS, NHID, adj0, xwT, gc1_b, h1, ADJ_SCALE, ADJ_INV);

    // 3. h1wT = (h1 @ gc2_w)^T  (pure fp16, transposed epilogue)
    h_gemm<false, false, true, true><<<dim3(NHID / BN, NROWS / BM), 256, DYN_P>>>(
        NHID, NROWS, h1, w2T, nullptr, h1wT, 1.0f);

    // 4. cat[:, :256] = adj1 @ h1w + gc2_b   (ldc = 768)
    hc_gemm<false, true, true, false><<<dim3(NHID / BN, NROWS / BM), 256, DYN_HC>>>(
        NROWS, NCAT, adj1, h1wT, gc2_b, cat, ADJ_SCALE, ADJ_INV);

    // 5. cat[:, 256:] = target_feats
    concat_h<<<(NROWS * NFEAT / 2 + 255) / 256, 256>>>(target, cat);

    // 6. o4 = relu(cat @ lin1_w + lin1_b)
    h_gemm<true, true, true, false><<<dim3(NCAT / BN, NROWS / BM), 256, DYN_P>>>(
        NCAT, NCAT, cat, l1T, lin1_b, o4, 1.0f);

    // 7. o5 = relu(o4 @ lin2_w + lin2_b)
    h_gemm<true, true, true, false><<<dim3(NCAT / BN, NROWS / BM), 256, DYN_P>>>(
        NCAT, NCAT, o4, l2T, lin2_b, o5, 1.0f);

    // 8. out = o5 @ lin3_w + lin3_b   (fp32 out)
    h_gemm<false, true, false, false><<<dim3(NFEAT / BN, NROWS / BM), 256, DYN_P>>>(
        NCAT, NFEAT, o5, l3T, lin3_b, out, 1.0f);

    // 9. log_softmax in place
    log_softmax_rows<<<NROWS, 256>>>(out);
}

// round 7
// speedup vs baseline: 5.4703x; 1.0224x over previous
#include <cuda_runtime.h>
#include <cuda_fp16.h>
#include <math.h>
#include <stdint.h>

// Problem dims (fixed per reference)
#define NROWS 8192
#define NFEAT 512
#define NHID  256
#define NCAT  768   // NHID + NFEAT

// ---------------------------------------------------------------------------
// Scratch (static device globals)
// ---------------------------------------------------------------------------
__device__ __half g_xwT [NHID * NROWS];
__device__ __half g_h1  [NROWS * NHID];
__device__ __half g_h1wT[NHID * NROWS];
__device__ __half g_cat [NROWS * NCAT];
__device__ __half g_o4  [NROWS * NCAT];
__device__ __half g_o5  [NROWS * NCAT];
__device__ __half g_w1T [NHID * NFEAT];
__device__ __half g_w2T [NHID * NHID];
__device__ __half g_l1T [NCAT * NCAT];
__device__ __half g_l2T [NCAT * NCAT];
__device__ __half g_l3T [NFEAT * NCAT];

// ---------------------------------------------------------------------------
// Helpers (baseline PTX only)
// ---------------------------------------------------------------------------
__device__ __forceinline__ uint32_t smem_u32(const void* p) {
    uint32_t a;
    asm("{ .reg .u64 t; cvta.to.shared.u64 t, %1; cvt.u32.u64 %0, t; }"
        : "=r"(a) : "l"(p));
    return a;
}
__device__ __forceinline__ void cpasync16(uint32_t dst, const void* src) {
    asm volatile("cp.async.cg.shared.global [%0], [%1], 16;" :: "r"(dst), "l"(src));
}
__device__ __forceinline__ void cp_commit() {
    asm volatile("cp.async.commit_group;" ::: "memory");
}
__device__ __forceinline__ void cp_wait2() {
    asm volatile("cp.async.wait_group 2;" ::: "memory");
}
__device__ __forceinline__ void cp_wait0() {
    asm volatile("cp.async.wait_group 0;" ::: "memory");
}
__device__ __forceinline__ void ldsm_x4(uint32_t* r, uint32_t addr) {
    asm volatile("ldmatrix.sync.aligned.m8n8.x4.shared.b16 {%0,%1,%2,%3}, [%4];"
                 : "=r"(r[0]), "=r"(r[1]), "=r"(r[2]), "=r"(r[3]) : "r"(addr));
}
__device__ __forceinline__ void mma_f16(float* c, const uint32_t* a, const uint32_t* b) {
    asm volatile(
        "mma.sync.aligned.m16n8k16.row.col.f32.f16.f16.f32 "
        "{%0,%1,%2,%3}, {%4,%5,%6,%7}, {%8,%9}, {%0,%1,%2,%3};"
        : "+f"(c[0]), "+f"(c[1]), "+f"(c[2]), "+f"(c[3])
        : "r"(a[0]), "r"(a[1]), "r"(a[2]), "r"(a[3]), "r"(b[0]), "r"(b[1]));
}
__device__ __forceinline__ uint32_t h2u(__half2 h) { return *(uint32_t*)&h; }

// ---------------------------------------------------------------------------
// Tiling: BM=64, BN=128, BK=32, 256 threads (8 warps 2x4), warp tile 32x32.
// fp16 tile row = 32 halfs (64B) + 16B pad = 80B  -> conflict-free ldmatrix.
// ---------------------------------------------------------------------------
#define BM 64
#define BN 128
#define BK 32
#define ROWH 80
#define A_TILE (BM * ROWH)          // 5120
#define B_TILE (BN * ROWH)          // 10240
// pure fp16 kernel: 4-stage {A16,B16}
#define P_STAGE (A_TILE + B_TILE)   // 15360
#define DYN_P (4 * P_STAGE)         // 61440
// convert kernel: 2-stage A16 + 4-stage B16
#define HC_B_OFF (2 * A_TILE)       // 10240
#define DYN_HC (HC_B_OFF + 4 * B_TILE)  // 51200

// A half tile: 64 rows x 4 chunks = 256, 1/thread
__device__ __forceinline__ void load_a_tile(uint32_t base, int tid,
                                            const __half* rowp, int K, int k0) {
    const int row = tid >> 2, q = tid & 3;
    cpasync16(base + row * ROWH + q * 16, rowp + (size_t)row * K + k0 + q * 8);
}
// B half tile: 128 rows x 4 chunks = 512, 2/thread
__device__ __forceinline__ void load_b_tile(uint32_t base, int tid,
                                            const __half* rowp, int K, int k0) {
    #pragma unroll
    for (int i = 0; i < 2; i++) {
        const int c = tid + i * 256;
        const int row = c >> 2, q = c & 3;
        cpasync16(base + row * ROWH + q * 16, rowp + (size_t)row * K + k0 + q * 8);
    }
}

// A-fp32: 8 consecutive floats per thread (2x LDG.128)
__device__ __forceinline__ void ldg8(float* ar, const float* p) {
    float4 v0 = ((const float4*)p)[0];
    float4 v1 = ((const float4*)p)[1];
    ar[0] = v0.x; ar[1] = v0.y; ar[2] = v0.z; ar[3] = v0.w;
    ar[4] = v1.x; ar[5] = v1.y; ar[6] = v1.z; ar[7] = v1.w;
}
// convert 8 floats * alpha -> 8 halfs -> 1x STS.128
__device__ __forceinline__ void cvt_sts(const float* ar, uint32_t dst, float alpha) {
    uint32_t o[4];
    #pragma unroll
    for (int i = 0; i < 4; i++)
        o[i] = h2u(__floats2half2_rn(ar[2 * i] * alpha, ar[2 * i + 1] * alpha));
    asm volatile("st.shared.v4.b32 [%0], {%1,%2,%3,%4};"
                 :: "r"(dst), "r"(o[0]), "r"(o[1]), "r"(o[2]), "r"(o[3]));
}

// ---- mainloop body: ldsm + mma over one BK=32 tile (warp tile 32x32) ----
__device__ __forceinline__ void mma_tile(float acc[2][4][4],
                                         uint32_t aBase, uint32_t bBase4) {
    #pragma unroll
    for (int ks = 0; ks < 2; ks++) {
        uint32_t af[2][4], bf[4][2];
        #pragma unroll
        for (int mt = 0; mt < 2; mt++)
            ldsm_x4(af[mt], aBase + mt * (16 * ROWH) + ks * 32);
        #pragma unroll
        for (int p = 0; p < 2; p++) {
            uint32_t q[4];
            ldsm_x4(q, bBase4 + p * (16 * ROWH) + ks * 32);
            bf[2 * p][0] = q[0]; bf[2 * p][1] = q[1];
            bf[2 * p + 1][0] = q[2]; bf[2 * p + 1][1] = q[3];
        }
        #pragma unroll
        for (int mt = 0; mt < 2; mt++)
            #pragma unroll
            for (int nt = 0; nt < 4; nt++)
                mma_f16(acc[mt][nt], af[mt], bf[nt]);
    }
}

// ---- epilogue: normal (direct) or transposed (smem-staged) ----
template <bool RELU, bool BIAS, bool HALF_OUT, bool TRANS>
__device__ __forceinline__ void epilogue(float acc[2][4][4], float scale,
                                         const float* bias, void* C, int ldc,
                                         int m0, int n0, int wm, int wn,
                                         int lane, int wid, uint8_t* scratch) {
    if (!TRANS) {
        const int rbase = m0 + wm * 32 + (lane >> 2);
        const int cbase = n0 + wn * 32 + 2 * (lane & 3);
        #pragma unroll
        for (int mt = 0; mt < 2; mt++) {
            #pragma unroll
            for (int nt = 0; nt < 4; nt++) {
                const int col = cbase + nt * 8;
                float b0 = 0.0f, b1 = 0.0f;
                if (BIAS) { b0 = bias[col]; b1 = bias[col + 1]; }
                float v0 = acc[mt][nt][0] * scale + b0;
                float v1 = acc[mt][nt][1] * scale + b1;
                float v2 = acc[mt][nt][2] * scale + b0;
                float v3 = acc[mt][nt][3] * scale + b1;
                if (RELU) {
                    v0 = fmaxf(v0, 0.0f); v1 = fmaxf(v1, 0.0f);
                    v2 = fmaxf(v2, 0.0f); v3 = fmaxf(v3, 0.0f);
                }
                const int row = rbase + mt * 16;
                if (HALF_OUT) {
                    __half* Ch = (__half*)C;
                    *(__half2*)(Ch + (size_t)row * ldc + col)       = __floats2half2_rn(v0, v1);
                    *(__half2*)(Ch + (size_t)(row + 8) * ldc + col) = __floats2half2_rn(v2, v3);
                } else {
                    float* Cf = (float*)C;
                    *(float2*)(Cf + (size_t)row * ldc + col)       = make_float2(v0, v1);
                    *(float2*)(Cf + (size_t)(row + 8) * ldc + col) = make_float2(v2, v3);
                }
            }
        }
    } else {
        // C^T output (half only, no bias/relu; scale applied).
        // Per-warp 32(cols) x 32(rows) scratch, row stride 40 halfs.
        __half* sw = (__half*)scratch + (size_t)wid * (32 * 40);
        #pragma unroll
        for (int mt = 0; mt < 2; mt++) {
            #pragma unroll
            for (int nt = 0; nt < 4; nt++) {
                const int r = (lane >> 2) + mt * 16;
                const int c = 2 * (lane & 3) + nt * 8;
                sw[(size_t)c * 40 + r]           = __float2half(acc[mt][nt][0] * scale);
                sw[(size_t)(c + 1) * 40 + r]     = __float2half(acc[mt][nt][1] * scale);
                sw[(size_t)c * 40 + r + 8]       = __float2half(acc[mt][nt][2] * scale);
                sw[(size_t)(c + 1) * 40 + r + 8] = __float2half(acc[mt][nt][3] * scale);
            }
        }
        __syncwarp();
        __half* dst = (__half*)C + (size_t)(n0 + wn * 32 + lane) * ldc + m0 + wm * 32;
        const uint4* srow = (const uint4*)(sw + (size_t)lane * 40);
        uint4* d4 = (uint4*)dst;
        #pragma unroll
        for (int i = 0; i < 4; i++) d4[i] = srow[i];
    }
}

// ---------------------------------------------------------------------------
// Pure fp16 GEMM: C = A_h[M,K] @ Bt_h[N,K]^T * scale (+bias)(+relu)
// One __syncthreads per iteration (shifted cp.async wait).
// ---------------------------------------------------------------------------
template <bool RELU, bool BIAS, bool HALF_OUT, bool TRANS>
__global__ __launch_bounds__(256, 2)
void h_gemm(int K, int ldc,
            const __half* __restrict__ A, const __half* __restrict__ Bt,
            const float* __restrict__ bias, void* __restrict__ C, float scale)
{
    extern __shared__ __align__(16) uint8_t dsraw[];
    const uint32_t smem = smem_u32(dsraw);
    const int tid = threadIdx.x, wid = tid >> 5, lane = tid & 31;
    const int wm = wid >> 2, wn = wid & 3;
    const int m0 = blockIdx.y * BM, n0 = blockIdx.x * BN;
    const int KT = K / BK;

    const __half* Arow = A + (size_t)m0 * K;
    const __half* Brow = Bt + (size_t)n0 * K;

    float acc[2][4][4];
    #pragma unroll
    for (int mt = 0; mt < 2; mt++)
        #pragma unroll
        for (int nt = 0; nt < 4; nt++)
            #pragma unroll
            for (int i = 0; i < 4; i++) acc[mt][nt][i] = 0.0f;

    const uint32_t aOff = (uint32_t)(wm * 32 + (lane & 15)) * ROWH + (lane >> 4) * 16;
    const uint32_t bOff4 = (uint32_t)(wn * 32 + (lane & 7) + ((lane >> 4) & 1) * 8) * ROWH
                         + ((lane >> 3) & 1) * 16;

    #pragma unroll
    for (int tt = 0; tt < 3; tt++) {
        const uint32_t st = smem + (uint32_t)tt * P_STAGE;
        load_a_tile(st, tid, Arow, K, tt * BK);
        load_b_tile(st + A_TILE, tid, Brow, K, tt * BK);
        cp_commit();
    }
    cp_wait2();                                    // tile 0 landed (this thread)

    for (int t = 0; t < KT; t++) {
        __syncthreads();                           // publish tile t; free stage (t-1)&3
        if (t + 3 < KT) {
            const uint32_t st = smem + (uint32_t)((t + 3) & 3) * P_STAGE;
            load_a_tile(st, tid, Arow, K, (t + 3) * BK);
            load_b_tile(st + A_TILE, tid, Brow, K, (t + 3) * BK);
        }
        cp_commit();
        const uint32_t st = smem + (uint32_t)(t & 3) * P_STAGE;
        mma_tile(acc, st + aOff, st + A_TILE + bOff4);
        cp_wait2();                                // tile t+1 landed (this thread)
    }
    cp_wait0();
    __syncthreads();                               // smem reusable as scratch
    epilogue<RELU, BIAS, HALF_OUT, TRANS>(acc, scale, bias, C, ldc,
                                          m0, n0, wm, wn, lane, wid, dsraw);
}

// ---------------------------------------------------------------------------
// fp32-A fused-convert GEMM: C = (alpha*A_f32) @ Bt_h^T * scale (+bias)(+relu)
// A loaded LDG->regs one tile ahead, converted into a 2-stage fp16 ring.
// One __syncthreads per iteration.
// ---------------------------------------------------------------------------
template <bool RELU, bool BIAS, bool HALF_OUT, bool TRANS>
__global__ __launch_bounds__(256, 2)
void hc_gemm(int K, int ldc,
             const float* __restrict__ A, const __half* __restrict__ Bt,
             const float* __restrict__ bias, void* __restrict__ C,
             float alpha, float scale)
{
    extern __shared__ __align__(16) uint8_t dsraw[];
    const uint32_t smem = smem_u32(dsraw);
    const int tid = threadIdx.x, wid = tid >> 5, lane = tid & 31;
    const int wm = wid >> 2, wn = wid & 3;
    const int m0 = blockIdx.y * BM, n0 = blockIdx.x * BN;
    const int KT = K / BK;

    const float* Arow = A + (size_t)m0 * K;
    const __half* Brow = Bt + (size_t)n0 * K;

    float acc[2][4][4];
    #pragma unroll
    for (int mt = 0; mt < 2; mt++)
        #pragma unroll
        for (int nt = 0; nt < 4; nt++)
            #pragma unroll
            for (int i = 0; i < 4; i++) acc[mt][nt][i] = 0.0f;

    const uint32_t aOff = (uint32_t)(wm * 32 + (lane & 15)) * ROWH + (lane >> 4) * 16;
    const uint32_t bOff4 = (uint32_t)(wn * 32 + (lane & 7) + ((lane >> 4) & 1) * 8) * ROWH
                         + ((lane >> 3) & 1) * 16;

    // convert mapping: 64 rows x 32 floats; 4 threads/row, 8 floats each
    const int crow = tid >> 2, cq = tid & 3;
    const float* aptr0 = Arow + (size_t)crow * K + cq * 8;
    const uint32_t cvtDstBase = smem + crow * ROWH + cq * 16;

    float ar[8];
    // prologue
    ldg8(ar, aptr0);                                          // tile 0 -> regs
    load_b_tile(smem + HC_B_OFF, tid, Brow, K, 0);            cp_commit();
    load_b_tile(smem + HC_B_OFF + B_TILE, tid, Brow, K, BK);  cp_commit();
    load_b_tile(smem + HC_B_OFF + 2 * B_TILE, tid, Brow, K, 2 * BK); cp_commit();
    cvt_sts(ar, cvtDstBase, alpha);                           // tile 0 -> A16[0]
    if (KT > 1) ldg8(ar, aptr0 + BK);                         // tile 1 -> regs
    cp_wait2();                                               // B0 landed (this thread)

    for (int t = 0; t < KT; t++) {
        __syncthreads();             // publish A16[t&1] + B tile t; free A16[(t+1)&1]
        if (t + 1 < KT)
            cvt_sts(ar, cvtDstBase + (uint32_t)((t + 1) & 1) * A_TILE, alpha);
        if (t + 2 < KT)
            ldg8(ar, aptr0 + (size_t)(t + 2) * BK);
        if (t + 3 < KT)
            load_b_tile(smem + HC_B_OFF + (uint32_t)((t + 3) & 3) * B_TILE,
                        tid, Brow, K, (t + 3) * BK);
        cp_commit();
        mma_tile(acc, smem + (uint32_t)(t & 1) * A_TILE + aOff,
                 smem + HC_B_OFF + (uint32_t)(t & 3) * B_TILE + bOff4);
        cp_wait2();                  // B tile t+1 landed (this thread)
    }
    cp_wait0();
    __syncthreads();
    epilogue<RELU, BIAS, HALF_OUT, TRANS>(acc, scale, bias, C, ldc,
                                          m0, n0, wm, wn, lane, wid, dsraw);
}

// ---------------------------------------------------------------------------
// fp32 -> fp16 transposed copy (weights): out[C,R] = (half) in[R,C]^T
// ---------------------------------------------------------------------------
__global__ __launch_bounds__(256) void transpose_cvt(const float* __restrict__ in,
                                                     __half* __restrict__ out,
                                                     int R, int C)
{
    __shared__ float t[32][33];
    const int bx = blockIdx.x * 32, by = blockIdx.y * 32;
    const int tx = threadIdx.x, ty = threadIdx.y;
    #pragma unroll
    for (int i = 0; i < 32; i += 8)
        t[ty + i][tx] = in[(size_t)(by + ty + i) * C + bx + tx];
    __syncthreads();
    #pragma unroll
    for (int i = 0; i < 32; i += 8)
        out[(size_t)(bx + ty + i) * R + by + tx] = __float2half(t[tx][ty + i]);
}

// concat: cat[:, NHID:] = (half) target
__global__ void concat_h(const float* __restrict__ target, __half* __restrict__ cat)
{
    int idx = blockIdx.x * blockDim.x + threadIdx.x;       // half2 units
    if (idx >= NROWS * NFEAT / 2) return;
    int r = idx / (NFEAT / 2);
    int c2 = idx % (NFEAT / 2);
    float2 v = ((const float2*)target)[idx];
    *(__half2*)(cat + (size_t)r * NCAT + NHID + c2 * 2) = __floats2half2_rn(v.x, v.y);
}

// ---------------------------------------------------------------------------
// Row-wise log_softmax over NFEAT=512 columns, in place (fp32).
// ---------------------------------------------------------------------------
__global__ __launch_bounds__(256) void log_softmax_rows(float* __restrict__ io)
{
    const int row = blockIdx.x;
    float* x = io + (size_t)row * NFEAT;
    const int tid = threadIdx.x;
    __shared__ float red[8];

    float m = -INFINITY;
    for (int c = tid; c < NFEAT; c += 256) m = fmaxf(m, x[c]);
    #pragma unroll
    for (int o = 16; o; o >>= 1) m = fmaxf(m, __shfl_xor_sync(0xFFFFFFFFu, m, o));
    if ((tid & 31) == 0) red[tid >> 5] = m;
    __syncthreads();
    float rowmax = red[0];
    #pragma unroll
    for (int i = 1; i < 8; i++) rowmax = fmaxf(rowmax, red[i]);
    __syncthreads();

    float s = 0.0f;
    for (int c = tid; c < NFEAT; c += 256) s += expf(x[c] - rowmax);
    #pragma unroll
    for (int o = 16; o; o >>= 1) s += __shfl_xor_sync(0xFFFFFFFFu, s, o);
    if ((tid & 31) == 0) red[tid >> 5] = s;
    __syncthreads();
    float tot = 0.0f;
    #pragma unroll
    for (int i = 0; i < 8; i++) tot += red[i];
    const float lse = logf(tot) + rowmax;

    for (int c = tid; c < NFEAT; c += 256) x[c] = x[c] - lse;
}

// ---------------------------------------------------------------------------
// Launch
// ---------------------------------------------------------------------------
#define ADJ_SCALE 8192.0f
#define ADJ_INV   (1.0f / 8192.0f)

extern "C" void kernel_launch(void* const* d_in, const int* in_sizes, int n_in,
                              void* d_out, int out_size)
{
    const float* x      = (const float*)d_in[0];
    const float* target = (const float*)d_in[1];
    const float* adj0   = (const float*)d_in[2];
    const float* adj1   = (const float*)d_in[3];
    const float* gc1_w  = (const float*)d_in[4];
    const float* gc1_b  = (const float*)d_in[5];
    const float* gc2_w  = (const float*)d_in[6];
    const float* gc2_b  = (const float*)d_in[7];
    const float* lin1_w = (const float*)d_in[8];
    const float* lin1_b = (const float*)d_in[9];
    const float* lin2_w = (const float*)d_in[10];
    const float* lin2_b = (const float*)d_in[11];
    const float* lin3_w = (const float*)d_in[12];
    const float* lin3_b = (const float*)d_in[13];
    float* out = (float*)d_out;

    __half *xwT, *h1, *h1wT, *cat, *o4, *o5;
    __half *w1T, *w2T, *l1T, *l2T, *l3T;
    cudaGetSymbolAddress((void**)&xwT,  g_xwT);
    cudaGetSymbolAddress((void**)&h1,   g_h1);
    cudaGetSymbolAddress((void**)&h1wT, g_h1wT);
    cudaGetSymbolAddress((void**)&cat,  g_cat);
    cudaGetSymbolAddress((void**)&o4,   g_o4);
    cudaGetSymbolAddress((void**)&o5,   g_o5);
    cudaGetSymbolAddress((void**)&w1T,  g_w1T);
    cudaGetSymbolAddress((void**)&w2T,  g_w2T);
    cudaGetSymbolAddress((void**)&l1T,  g_l1T);
    cudaGetSymbolAddress((void**)&l2T,  g_l2T);
    cudaGetSymbolAddress((void**)&l3T,  g_l3T);

    cudaFuncSetAttribute(h_gemm<false, false, true, true>,   cudaFuncAttributeMaxDynamicSharedMemorySize, DYN_P);
    cudaFuncSetAttribute(h_gemm<true,  true,  true, false>,  cudaFuncAttributeMaxDynamicSharedMemorySize, DYN_P);
    cudaFuncSetAttribute(h_gemm<false, true,  false, false>, cudaFuncAttributeMaxDynamicSharedMemorySize, DYN_P);
    cudaFuncSetAttribute(hc_gemm<false, false, true, true>,  cudaFuncAttributeMaxDynamicSharedMemorySize, DYN_HC);
    cudaFuncSetAttribute(hc_gemm<true,  true,  true, false>, cudaFuncAttributeMaxDynamicSharedMemorySize, DYN_HC);
    cudaFuncSetAttribute(hc_gemm<false, true,  true, false>, cudaFuncAttributeMaxDynamicSharedMemorySize, DYN_HC);

    const dim3 tblk(32, 8);

    // Weight transposes + fp16 convert ([K,N] -> [N,K] half)
    transpose_cvt<<<dim3(NHID / 32, NFEAT / 32), tblk>>>(gc1_w, w1T, NFEAT, NHID);
    transpose_cvt<<<dim3(NHID / 32, NHID / 32), tblk>>>(gc2_w, w2T, NHID, NHID);
    transpose_cvt<<<dim3(NCAT / 32, NCAT / 32), tblk>>>(lin1_w, l1T, NCAT, NCAT);
    transpose_cvt<<<dim3(NCAT / 32, NCAT / 32), tblk>>>(lin2_w, l2T, NCAT, NCAT);
    transpose_cvt<<<dim3(NFEAT / 32, NCAT / 32), tblk>>>(lin3_w, l3T, NCAT, NFEAT);

    // 1. xwT = (x @ gc1_w)^T   (fp32 A, transposed epilogue, ldc = NROWS)
    hc_gemm<false, false, true, true><<<dim3(NHID / BN, NROWS / BM), 256, DYN_HC>>>(
        NFEAT, NROWS, x, w1T, nullptr, xwT, 1.0f, 1.0f);

    // 2. h1 = relu(adj0 @ xw + gc1_b)   (adj scaled 2^13, epilogue 2^-13)
    hc_gemm<true, true, true, false><<<dim3(NHID / BN, NROWS / BM), 256, DYN_HC>>>(
        NROWS, NHID, adj0, xwT, gc1_b, h1, ADJ_SCALE, ADJ_INV);

    // 3. h1wT = (h1 @ gc2_w)^T  (pure fp16, transposed epilogue)
    h_gemm<false, false, true, true><<<dim3(NHID / BN, NROWS / BM), 256, DYN_P>>>(
        NHID, NROWS, h1, w2T, nullptr, h1wT, 1.0f);

    // 4. cat[:, :256] = adj1 @ h1w + gc2_b   (ldc = 768)
    hc_gemm<false, true, true, false><<<dim3(NHID / BN, NROWS / BM), 256, DYN_HC>>>(
        NROWS, NCAT, adj1, h1wT, gc2_b, cat, ADJ_SCALE, ADJ_INV);

    // 5. cat[:, 256:] = target_feats
    concat_h<<<(NROWS * NFEAT / 2 + 255) / 256, 256>>>(target, cat);

    // 6. o4 = relu(cat @ lin1_w + lin1_b)
    h_gemm<true, true, true, false><<<dim3(NCAT / BN, NROWS / BM), 256, DYN_P>>>(
        NCAT, NCAT, cat, l1T, lin1_b, o4, 1.0f);

    // 7. o5 = relu(o4 @ lin2_w + lin2_b)
    h_gemm<true, true, true, false><<<dim3(NCAT / BN, NROWS / BM), 256, DYN_P>>>(
        NCAT, NCAT, o4, l2T, lin2_b, o5, 1.0f);

    // 8. out = o5 @ lin3_w + lin3_b   (fp32 out)
    h_gemm<false, true, false, false><<<dim3(NFEAT / BN, NROWS / BM), 256, DYN_P>>>(
        NCAT, NFEAT, o5, l3T, lin3_b, out, 1.0f);

    // 9. log_softmax in place
    log_softmax_rows<<<NROWS, 256>>>(out);
}

// round 8
// speedup vs baseline: 6.0249x; 1.1014x over previous
#include <cuda_runtime.h>
#include <cuda_fp16.h>
#include <math.h>
#include <stdint.h>

// Problem dims (fixed per reference)
#define NROWS 8192
#define NFEAT 512
#define NHID  256
#define NCAT  768   // NHID + NFEAT

// ---------------------------------------------------------------------------
// Scratch (static device globals)
// ---------------------------------------------------------------------------
__device__ __half g_xwT [NHID * NROWS];
__device__ __half g_h1  [NROWS * NHID];
__device__ __half g_h1wT[NHID * NROWS];
__device__ __half g_cat [NROWS * NCAT];
__device__ __half g_o4  [NROWS * NCAT];
__device__ __half g_o5  [NROWS * NCAT];
__device__ __half g_w1T [NHID * NFEAT];
__device__ __half g_w2T [NHID * NHID];
__device__ __half g_l1T [NCAT * NCAT];
__device__ __half g_l2T [NCAT * NCAT];
__device__ __half g_l3T [NFEAT * NCAT];

// ---------------------------------------------------------------------------
// Helpers (baseline PTX only)
// ---------------------------------------------------------------------------
__device__ __forceinline__ uint32_t smem_u32(const void* p) {
    uint32_t a;
    asm("{ .reg .u64 t; cvta.to.shared.u64 t, %1; cvt.u32.u64 %0, t; }"
        : "=r"(a) : "l"(p));
    return a;
}
__device__ __forceinline__ void cpasync16(uint32_t dst, const void* src) {
    asm volatile("cp.async.cg.shared.global [%0], [%1], 16;" :: "r"(dst), "l"(src));
}
__device__ __forceinline__ void cp_commit() {
    asm volatile("cp.async.commit_group;" ::: "memory");
}
__device__ __forceinline__ void cp_wait1() {
    asm volatile("cp.async.wait_group 1;" ::: "memory");
}
__device__ __forceinline__ void cp_wait2() {
    asm volatile("cp.async.wait_group 2;" ::: "memory");
}
__device__ __forceinline__ void cp_wait0() {
    asm volatile("cp.async.wait_group 0;" ::: "memory");
}
__device__ __forceinline__ void ldsm_x4(uint32_t* r, uint32_t addr) {
    asm volatile("ldmatrix.sync.aligned.m8n8.x4.shared.b16 {%0,%1,%2,%3}, [%4];"
                 : "=r"(r[0]), "=r"(r[1]), "=r"(r[2]), "=r"(r[3]) : "r"(addr));
}
__device__ __forceinline__ void mma_f16(float* c, const uint32_t* a, const uint32_t* b) {
    asm volatile(
        "mma.sync.aligned.m16n8k16.row.col.f32.f16.f16.f32 "
        "{%0,%1,%2,%3}, {%4,%5,%6,%7}, {%8,%9}, {%0,%1,%2,%3};"
        : "+f"(c[0]), "+f"(c[1]), "+f"(c[2]), "+f"(c[3])
        : "r"(a[0]), "r"(a[1]), "r"(a[2]), "r"(a[3]), "r"(b[0]), "r"(b[1]));
}
__device__ __forceinline__ uint32_t h2u(__half2 h) { return *(uint32_t*)&h; }

// ---------------------------------------------------------------------------
// Tiling: BM=64, BN=128, BK=64, 256 threads (8 warps 2x4), warp tile 32x32.
// fp16 tile row = 64 halfs (128B) + 16B pad = 144B -> conflict-free ldmatrix
// (144/16 = 9 == 1 mod 8).
// ---------------------------------------------------------------------------
#define BM 64
#define BN 128
#define BK 64
#define ROWB 144
#define A_TILE (BM * ROWB)          // 9216
#define B_TILE (BN * ROWB)          // 18432
// pure fp16 kernel: 3-stage {A16,B16}
#define P_STAGE (A_TILE + B_TILE)   // 27648
#define DYN_P (3 * P_STAGE)         // 82944  -> occupancy 2
// convert kernel: 2-stage A16 + 4-stage B16
#define HC_B_OFF (2 * A_TILE)       // 18432
#define DYN_HC (HC_B_OFF + 4 * B_TILE)  // 92160 -> occupancy 2

// A half tile: 64 rows x 8 chunks = 512, 2/thread
__device__ __forceinline__ void load_a_tile(uint32_t base, int tid,
                                            const __half* rowp, int K, int k0) {
    #pragma unroll
    for (int i = 0; i < 2; i++) {
        const int c = tid + i * 256;
        const int row = c >> 3, q = c & 7;
        cpasync16(base + row * ROWB + q * 16, rowp + (size_t)row * K + k0 + q * 8);
    }
}
// B half tile: 128 rows x 8 chunks = 1024, 4/thread
__device__ __forceinline__ void load_b_tile(uint32_t base, int tid,
                                            const __half* rowp, int K, int k0) {
    #pragma unroll
    for (int i = 0; i < 4; i++) {
        const int c = tid + i * 256;
        const int row = c >> 3, q = c & 7;
        cpasync16(base + row * ROWB + q * 16, rowp + (size_t)row * K + k0 + q * 8);
    }
}

// A-fp32: 16 consecutive floats per thread (4x LDG.128)
__device__ __forceinline__ void ldg16(float* ar, const float* p) {
    float4 v0 = ((const float4*)p)[0];
    float4 v1 = ((const float4*)p)[1];
    float4 v2 = ((const float4*)p)[2];
    float4 v3 = ((const float4*)p)[3];
    ar[0]  = v0.x; ar[1]  = v0.y; ar[2]  = v0.z; ar[3]  = v0.w;
    ar[4]  = v1.x; ar[5]  = v1.y; ar[6]  = v1.z; ar[7]  = v1.w;
    ar[8]  = v2.x; ar[9]  = v2.y; ar[10] = v2.z; ar[11] = v2.w;
    ar[12] = v3.x; ar[13] = v3.y; ar[14] = v3.z; ar[15] = v3.w;
}
// convert 16 floats * alpha -> 16 halfs -> 2x STS.128
__device__ __forceinline__ void cvt_sts(const float* ar, uint32_t dst, float alpha) {
    uint32_t o[8];
    #pragma unroll
    for (int i = 0; i < 8; i++)
        o[i] = h2u(__floats2half2_rn(ar[2 * i] * alpha, ar[2 * i + 1] * alpha));
    asm volatile("st.shared.v4.b32 [%0], {%1,%2,%3,%4};"
                 :: "r"(dst), "r"(o[0]), "r"(o[1]), "r"(o[2]), "r"(o[3]));
    asm volatile("st.shared.v4.b32 [%0], {%1,%2,%3,%4};"
                 :: "r"(dst + 16), "r"(o[4]), "r"(o[5]), "r"(o[6]), "r"(o[7]));
}

// ---- mainloop body: ldsm + mma over one BK=64 tile (warp tile 32x32) ----
__device__ __forceinline__ void mma_tile(float acc[2][4][4],
                                         uint32_t aBase, uint32_t bBase4) {
    #pragma unroll
    for (int ks = 0; ks < 4; ks++) {
        uint32_t af[2][4], bf[4][2];
        #pragma unroll
        for (int mt = 0; mt < 2; mt++)
            ldsm_x4(af[mt], aBase + mt * (16 * ROWB) + ks * 32);
        #pragma unroll
        for (int p = 0; p < 2; p++) {
            uint32_t q[4];
            ldsm_x4(q, bBase4 + p * (16 * ROWB) + ks * 32);
            bf[2 * p][0] = q[0]; bf[2 * p][1] = q[1];
            bf[2 * p + 1][0] = q[2]; bf[2 * p + 1][1] = q[3];
        }
        #pragma unroll
        for (int mt = 0; mt < 2; mt++)
            #pragma unroll
            for (int nt = 0; nt < 4; nt++)
                mma_f16(acc[mt][nt], af[mt], bf[nt]);
    }
}

// ---- epilogue: normal (direct) or transposed (smem-staged) ----
template <bool RELU, bool BIAS, bool HALF_OUT, bool TRANS>
__device__ __forceinline__ void epilogue(float acc[2][4][4], float scale,
                                         const float* bias, void* C, int ldc,
                                         int m0, int n0, int wm, int wn,
                                         int lane, int wid, uint8_t* scratch) {
    if (!TRANS) {
        const int rbase = m0 + wm * 32 + (lane >> 2);
        const int cbase = n0 + wn * 32 + 2 * (lane & 3);
        #pragma unroll
        for (int mt = 0; mt < 2; mt++) {
            #pragma unroll
            for (int nt = 0; nt < 4; nt++) {
                const int col = cbase + nt * 8;
                float b0 = 0.0f, b1 = 0.0f;
                if (BIAS) { b0 = bias[col]; b1 = bias[col + 1]; }
                float v0 = acc[mt][nt][0] * scale + b0;
                float v1 = acc[mt][nt][1] * scale + b1;
                float v2 = acc[mt][nt][2] * scale + b0;
                float v3 = acc[mt][nt][3] * scale + b1;
                if (RELU) {
                    v0 = fmaxf(v0, 0.0f); v1 = fmaxf(v1, 0.0f);
                    v2 = fmaxf(v2, 0.0f); v3 = fmaxf(v3, 0.0f);
                }
                const int row = rbase + mt * 16;
                if (HALF_OUT) {
                    __half* Ch = (__half*)C;
                    *(__half2*)(Ch + (size_t)row * ldc + col)       = __floats2half2_rn(v0, v1);
                    *(__half2*)(Ch + (size_t)(row + 8) * ldc + col) = __floats2half2_rn(v2, v3);
                } else {
                    float* Cf = (float*)C;
                    *(float2*)(Cf + (size_t)row * ldc + col)       = make_float2(v0, v1);
                    *(float2*)(Cf + (size_t)(row + 8) * ldc + col) = make_float2(v2, v3);
                }
            }
        }
    } else {
        // C^T output (half only, no bias/relu; scale applied).
        // Per-warp 32(cols) x 32(rows) scratch, row stride 40 halfs.
        __half* sw = (__half*)scratch + (size_t)wid * (32 * 40);
        #pragma unroll
        for (int mt = 0; mt < 2; mt++) {
            #pragma unroll
            for (int nt = 0; nt < 4; nt++) {
                const int r = (lane >> 2) + mt * 16;
                const int c = 2 * (lane & 3) + nt * 8;
                sw[(size_t)c * 40 + r]           = __float2half(acc[mt][nt][0] * scale);
                sw[(size_t)(c + 1) * 40 + r]     = __float2half(acc[mt][nt][1] * scale);
                sw[(size_t)c * 40 + r + 8]       = __float2half(acc[mt][nt][2] * scale);
                sw[(size_t)(c + 1) * 40 + r + 8] = __float2half(acc[mt][nt][3] * scale);
            }
        }
        __syncwarp();
        __half* dst = (__half*)C + (size_t)(n0 + wn * 32 + lane) * ldc + m0 + wm * 32;
        const uint4* srow = (const uint4*)(sw + (size_t)lane * 40);
        uint4* d4 = (uint4*)dst;
        #pragma unroll
        for (int i = 0; i < 4; i++) d4[i] = srow[i];
    }
}

// ---------------------------------------------------------------------------
// Pure fp16 GEMM: C = A_h[M,K] @ Bt_h[N,K]^T * scale (+bias)(+relu)
// 3-stage pipeline, one __syncthreads per iteration.  Requires K%64==0, KT>=2.
// ---------------------------------------------------------------------------
template <bool RELU, bool BIAS, bool HALF_OUT, bool TRANS>
__global__ __launch_bounds__(256, 2)
void h_gemm(int K, int ldc,
            const __half* __restrict__ A, const __half* __restrict__ Bt,
            const float* __restrict__ bias, void* __restrict__ C, float scale)
{
    extern __shared__ __align__(16) uint8_t dsraw[];
    const uint32_t smem = smem_u32(dsraw);
    const int tid = threadIdx.x, wid = tid >> 5, lane = tid & 31;
    const int wm = wid >> 2, wn = wid & 3;
    const int m0 = blockIdx.y * BM, n0 = blockIdx.x * BN;
    const int KT = K / BK;

    const __half* Arow = A + (size_t)m0 * K;
    const __half* Brow = Bt + (size_t)n0 * K;

    float acc[2][4][4];
    #pragma unroll
    for (int mt = 0; mt < 2; mt++)
        #pragma unroll
        for (int nt = 0; nt < 4; nt++)
            #pragma unroll
            for (int i = 0; i < 4; i++) acc[mt][nt][i] = 0.0f;

    const uint32_t aOff = (uint32_t)(wm * 32 + (lane & 15)) * ROWB + (lane >> 4) * 16;
    const uint32_t bOff4 = (uint32_t)(wn * 32 + (lane & 7) + ((lane >> 4) & 1) * 8) * ROWB
                         + ((lane >> 3) & 1) * 16;

    #pragma unroll
    for (int tt = 0; tt < 2; tt++) {
        const uint32_t st = smem + (uint32_t)tt * P_STAGE;
        load_a_tile(st, tid, Arow, K, tt * BK);
        load_b_tile(st + A_TILE, tid, Brow, K, tt * BK);
        cp_commit();
    }
    cp_wait1();                                    // tile 0 landed (this thread)

    int s = 0;                                     // stage of tile t
    for (int t = 0; t < KT; t++) {
        __syncthreads();                           // publish tile t; free stage (t-1)%3
        if (t + 2 < KT) {
            const int sw = (s + 2 >= 3) ? s - 1 : s + 2;
            const uint32_t st = smem + (uint32_t)sw * P_STAGE;
            load_a_tile(st, tid, Arow, K, (t + 2) * BK);
            load_b_tile(st + A_TILE, tid, Brow, K, (t + 2) * BK);
        }
        cp_commit();
        const uint32_t st = smem + (uint32_t)s * P_STAGE;
        mma_tile(acc, st + aOff, st + A_TILE + bOff4);
        cp_wait1();                                // tile t+1 landed (this thread)
        s = (s + 1 == 3) ? 0 : s + 1;
    }
    cp_wait0();
    __syncthreads();                               // smem reusable as scratch
    epilogue<RELU, BIAS, HALF_OUT, TRANS>(acc, scale, bias, C, ldc,
                                          m0, n0, wm, wn, lane, wid, dsraw);
}

// ---------------------------------------------------------------------------
// fp32-A fused-convert GEMM: C = (alpha*A_f32) @ Bt_h^T * scale (+bias)(+relu)
// A loaded LDG->regs one tile ahead, converted into a 2-stage fp16 ring;
// B in 4-stage cp.async ring.  One __syncthreads per iteration.  KT>=3.
// ---------------------------------------------------------------------------
template <bool RELU, bool BIAS, bool HALF_OUT, bool TRANS>
__global__ __launch_bounds__(256, 2)
void hc_gemm(int K, int ldc,
             const float* __restrict__ A, const __half* __restrict__ Bt,
             const float* __restrict__ bias, void* __restrict__ C,
             float alpha, float scale)
{
    extern __shared__ __align__(16) uint8_t dsraw[];
    const uint32_t smem = smem_u32(dsraw);
    const int tid = threadIdx.x, wid = tid >> 5, lane = tid & 31;
    const int wm = wid >> 2, wn = wid & 3;
    const int m0 = blockIdx.y * BM, n0 = blockIdx.x * BN;
    const int KT = K / BK;

    const float* Arow = A + (size_t)m0 * K;
    const __half* Brow = Bt + (size_t)n0 * K;

    float acc[2][4][4];
    #pragma unroll
    for (int mt = 0; mt < 2; mt++)
        #pragma unroll
        for (int nt = 0; nt < 4; nt++)
            #pragma unroll
            for (int i = 0; i < 4; i++) acc[mt][nt][i] = 0.0f;

    const uint32_t aOff = (uint32_t)(wm * 32 + (lane & 15)) * ROWB + (lane >> 4) * 16;
    const uint32_t bOff4 = (uint32_t)(wn * 32 + (lane & 7) + ((lane >> 4) & 1) * 8) * ROWB
                         + ((lane >> 3) & 1) * 16;

    // convert mapping: 64 rows x 64 floats; 4 threads/row, 16 floats each
    const int crow = tid >> 2, cq = tid & 3;
    const float* aptr0 = Arow + (size_t)crow * K + cq * 16;
    const uint32_t cvtDstBase = smem + crow * ROWB + cq * 32 + cq * 16 - cq * 16; // = smem + crow*ROWB + cq*32

    float ar[16];
    // prologue
    ldg16(ar, aptr0);                                          // tile 0 -> regs
    load_b_tile(smem + HC_B_OFF, tid, Brow, K, 0);             cp_commit();
    load_b_tile(smem + HC_B_OFF + B_TILE, tid, Brow, K, BK);   cp_commit();
    load_b_tile(smem + HC_B_OFF + 2 * B_TILE, tid, Brow, K, 2 * BK); cp_commit();
    cvt_sts(ar, cvtDstBase, alpha);                            // tile 0 -> A16[0]
    if (KT > 1) ldg16(ar, aptr0 + BK);                         // tile 1 -> regs
    cp_wait2();                                                // B0 landed (this thread)

    for (int t = 0; t < KT; t++) {
        __syncthreads();             // publish A16[t&1] + B tile t; free A16[(t+1)&1]
        if (t + 1 < KT)
            cvt_sts(ar, cvtDstBase + (uint32_t)((t + 1) & 1) * A_TILE, alpha);
        if (t + 2 < KT)
            ldg16(ar, aptr0 + (size_t)(t + 2) * BK);
        if (t + 3 < KT)
            load_b_tile(smem + HC_B_OFF + (uint32_t)((t + 3) & 3) * B_TILE,
                        tid, Brow, K, (t + 3) * BK);
        cp_commit();
        mma_tile(acc, smem + (uint32_t)(t & 1) * A_TILE + aOff,
                 smem + HC_B_OFF + (uint32_t)(t & 3) * B_TILE + bOff4);
        cp_wait2();                  // B tile t+1 landed (this thread)
    }
    cp_wait0();
    __syncthreads();
    epilogue<RELU, BIAS, HALF_OUT, TRANS>(acc, scale, bias, C, ldc,
                                          m0, n0, wm, wn, lane, wid, dsraw);
}

// ---------------------------------------------------------------------------
// Batched fp32 -> fp16 transposed copy for the 5 weight matrices.
// One launch; job selected by flat blockIdx.
// ---------------------------------------------------------------------------
struct TJob { const float* in; __half* out; int R; int C; int tileStart; };
struct TJobs { TJob j[5]; int total; };

__global__ __launch_bounds__(256) void transpose_all(TJobs jobs)
{
    __shared__ float t[32][33];
    int b = blockIdx.x;
    int ji = 0;
    #pragma unroll
    for (int i = 1; i < 5; i++) if (b >= jobs.j[i].tileStart) ji = i;
    const TJob jb = jobs.j[ji];
    const int rel = b - jb.tileStart;
    const int tilesX = jb.C / 32;
    const int bx = (rel % tilesX) * 32;   // C dim
    const int by = (rel / tilesX) * 32;   // R dim
    const int tx = threadIdx.x, ty = threadIdx.y;
    #pragma unroll
    for (int i = 0; i < 32; i += 8)
        t[ty + i][tx] = jb.in[(size_t)(by + ty + i) * jb.C + bx + tx];
    __syncthreads();
    #pragma unroll
    for (int i = 0; i < 32; i += 8)
        jb.out[(size_t)(bx + ty + i) * jb.R + by + tx] = __float2half(t[tx][ty + i]);
}

// concat: cat[:, NHID:] = (half) target
__global__ void concat_h(const float* __restrict__ target, __half* __restrict__ cat)
{
    int idx = blockIdx.x * blockDim.x + threadIdx.x;       // half2 units
    if (idx >= NROWS * NFEAT / 2) return;
    int r = idx / (NFEAT / 2);
    int c2 = idx % (NFEAT / 2);
    float2 v = ((const float2*)target)[idx];
    *(__half2*)(cat + (size_t)r * NCAT + NHID + c2 * 2) = __floats2half2_rn(v.x, v.y);
}

// ---------------------------------------------------------------------------
// Row-wise log_softmax over NFEAT=512 columns, in place (fp32).
// ---------------------------------------------------------------------------
__global__ __launch_bounds__(256) void log_softmax_rows(float* __restrict__ io)
{
    const int row = blockIdx.x;
    float* x = io + (size_t)row * NFEAT;
    const int tid = threadIdx.x;
    __shared__ float red[8];

    float m = -INFINITY;
    for (int c = tid; c < NFEAT; c += 256) m = fmaxf(m, x[c]);
    #pragma unroll
    for (int o = 16; o; o >>= 1) m = fmaxf(m, __shfl_xor_sync(0xFFFFFFFFu, m, o));
    if ((tid & 31) == 0) red[tid >> 5] = m;
    __syncthreads();
    float rowmax = red[0];
    #pragma unroll
    for (int i = 1; i < 8; i++) rowmax = fmaxf(rowmax, red[i]);
    __syncthreads();

    float s = 0.0f;
    for (int c = tid; c < NFEAT; c += 256) s += expf(x[c] - rowmax);
    #pragma unroll
    for (int o = 16; o; o >>= 1) s += __shfl_xor_sync(0xFFFFFFFFu, s, o);
    if ((tid & 31) == 0) red[tid >> 5] = s;
    __syncthreads();
    float tot = 0.0f;
    #pragma unroll
    for (int i = 0; i < 8; i++) tot += red[i];
    const float lse = logf(tot) + rowmax;

    for (int c = tid; c < NFEAT; c += 256) x[c] = x[c] - lse;
}

// ---------------------------------------------------------------------------
// Launch
// ---------------------------------------------------------------------------
#define ADJ_SCALE 8192.0f
#define ADJ_INV   (1.0f / 8192.0f)

extern "C" void kernel_launch(void* const* d_in, const int* in_sizes, int n_in,
                              void* d_out, int out_size)
{
    const float* x      = (const float*)d_in[0];
    const float* target = (const float*)d_in[1];
    const float* adj0   = (const float*)d_in[2];
    const float* adj1   = (const float*)d_in[3];
    const float* gc1_w  = (const float*)d_in[4];
    const float* gc1_b  = (const float*)d_in[5];
    const float* gc2_w  = (const float*)d_in[6];
    const float* gc2_b  = (const float*)d_in[7];
    const float* lin1_w = (const float*)d_in[8];
    const float* lin1_b = (const float*)d_in[9];
    const float* lin2_w = (const float*)d_in[10];
    const float* lin2_b = (const float*)d_in[11];
    const float* lin3_w = (const float*)d_in[12];
    const float* lin3_b = (const float*)d_in[13];
    float* out = (float*)d_out;

    __half *xwT, *h1, *h1wT, *cat, *o4, *o5;
    __half *w1T, *w2T, *l1T, *l2T, *l3T;
    cudaGetSymbolAddress((void**)&xwT,  g_xwT);
    cudaGetSymbolAddress((void**)&h1,   g_h1);
    cudaGetSymbolAddress((void**)&h1wT, g_h1wT);
    cudaGetSymbolAddress((void**)&cat,  g_cat);
    cudaGetSymbolAddress((void**)&o4,   g_o4);
    cudaGetSymbolAddress((void**)&o5,   g_o5);
    cudaGetSymbolAddress((void**)&w1T,  g_w1T);
    cudaGetSymbolAddress((void**)&w2T,  g_w2T);
    cudaGetSymbolAddress((void**)&l1T,  g_l1T);
    cudaGetSymbolAddress((void**)&l2T,  g_l2T);
    cudaGetSymbolAddress((void**)&l3T,  g_l3T);

    cudaFuncSetAttribute(h_gemm<false, false, true, true>,   cudaFuncAttributeMaxDynamicSharedMemorySize, DYN_P);
    cudaFuncSetAttribute(h_gemm<true,  true,  true, false>,  cudaFuncAttributeMaxDynamicSharedMemorySize, DYN_P);
    cudaFuncSetAttribute(h_gemm<false, true,  false, false>, cudaFuncAttributeMaxDynamicSharedMemorySize, DYN_P);
    cudaFuncSetAttribute(hc_gemm<false, false, true, true>,  cudaFuncAttributeMaxDynamicSharedMemorySize, DYN_HC);
    cudaFuncSetAttribute(hc_gemm<true,  true,  true, false>, cudaFuncAttributeMaxDynamicSharedMemorySize, DYN_HC);
    cudaFuncSetAttribute(hc_gemm<false, true,  true, false>, cudaFuncAttributeMaxDynamicSharedMemorySize, DYN_HC);

    // Batched weight transposes ([K,N] -> [N,K] half), one launch.
    TJobs jobs;
    jobs.j[0] = { gc1_w,  w1T, NFEAT, NHID, 0 };                              // 16x8  = 128
    jobs.j[1] = { gc2_w,  w2T, NHID,  NHID, 128 };                            // 8x8   = 64
    jobs.j[2] = { lin1_w, l1T, NCAT,  NCAT, 192 };                            // 24x24 = 576
    jobs.j[3] = { lin2_w, l2T, NCAT,  NCAT, 768 };                            // 24x24 = 576
    jobs.j[4] = { lin3_w, l3T, NCAT,  NFEAT, 1344 };                          // 24x16 = 384
    jobs.total = 1728;
    transpose_all<<<1728, dim3(32, 8)>>>(jobs);

    // 1. xwT = (x @ gc1_w)^T   (fp32 A, transposed epilogue, ldc = NROWS)
    hc_gemm<false, false, true, true><<<dim3(NHID / BN, NROWS / BM), 256, DYN_HC>>>(
        NFEAT, NROWS, x, w1T, nullptr, xwT, 1.0f, 1.0f);

    // 2. h1 = relu(adj0 @ xw + gc1_b)   (adj scaled 2^13, epilogue 2^-13)
    hc_gemm<true, true, true, false><<<dim3(NHID / BN, NROWS / BM), 256, DYN_HC>>>(
        NROWS, NHID, adj0, xwT, gc1_b, h1, ADJ_SCALE, ADJ_INV);

    // 3. h1wT = (h1 @ gc2_w)^T  (pure fp16, transposed epilogue, K=256 -> KT=4)
    h_gemm<false, false, true, true><<<dim3(NHID / BN, NROWS / BM), 256, DYN_P>>>(
        NHID, NROWS, h1, w2T, nullptr, h1wT, 1.0f);

    // 4. cat[:, :256] = adj1 @ h1w + gc2_b   (ldc = 768)
    hc_gemm<false, true, true, false><<<dim3(NHID / BN, NROWS / BM), 256, DYN_HC>>>(
        NROWS, NCAT, adj1, h1wT, gc2_b, cat, ADJ_SCALE, ADJ_INV);

    // 5. cat[:, 256:] = target_feats
    concat_h<<<(NROWS * NFEAT / 2 + 255) / 256, 256>>>(target, cat);

    // 6. o4 = relu(cat @ lin1_w + lin1_b)
    h_gemm<true, true, true, false><<<dim3(NCAT / BN, NROWS / BM), 256, DYN_P>>>(
        NCAT, NCAT, cat, l1T, lin1_b, o4, 1.0f);

    // 7. o5 = relu(o4 @ lin2_w + lin2_b)
    h_gemm<true, true, true, false><<<dim3(NCAT / BN, NROWS / BM), 256, DYN_P>>>(
        NCAT, NCAT, o4, l2T, lin2_b, o5, 1.0f);

    // 8. out = o5 @ lin3_w + lin3_b   (fp32 out)
    h_gemm<false, true, false, false><<<dim3(NFEAT / BN, NROWS / BM), 256, DYN_P>>>(
        NCAT, NFEAT, o5, l3T, lin3_b, out, 1.0f);

    // 9. log_softmax in place
    log_softmax_rows<<<NROWS, 256>>>(out);
}